// round 13
// baseline (speedup 1.0000x reference)
#include <cuda_runtime.h>
#include <math.h>
#include <stdint.h>

#define MROWS  16384
#define LSEQ   4096
#define BSZ    4
#define DIMC   384
#define DINNER 768
#define DSTATE 16
#define DTRANK 24

// ---------------- scratch (device globals; allocation-free) ----------------
__device__ float g_Wr_t  [768*384];    // reduce_W^T   (K=768, N=384)
__device__ float g_Win_t [384*1536];   // in_proj_W^T
__device__ float g_Winb_t[384*768];
__device__ float g_Winc_t[384*768];
__device__ float g_Wout_t[768*384];
__device__ float g_Wxp64 [768*64];     // x_proj_W^T padded  [768][64]
__device__ float g_Wxpc64[768*64];     // x_proj_c_W^T padded [768][64]
__device__ float g_Wdt_t [24*768];

__device__ float g_msn   [MROWS*384];
__device__ float g_pann  [MROWS*384];
__device__ float g_red   [MROWS*384];
__device__ float g_conn  [MROWS*384];
__device__ float g_xz    [(size_t)MROWS*1536];
__device__ float g_xbp   [MROWS*768];
__device__ float g_xcp   [MROWS*768];
__device__ float g_x     [MROWS*768];
__device__ float g_xb    [MROWS*768];
__device__ float g_xc    [MROWS*768];
__device__ float g_dbl   [MROWS*40];
__device__ float g_dt    [MROWS*768];
__device__ float g_cm    [MROWS*16];
__device__ float g_y     [MROWS*768];
__device__ float g_gf    [MROWS*384];

// ---------------- helpers ----------------
__device__ __forceinline__ float silu_f(float v) {
    return v / (1.f + __expf(-v));
}

// ---------------- weight transpose: out[k*N+n] = in[n*K+k] ----------------
__global__ void wt_transpose(const float* __restrict__ in, float* __restrict__ out,
                             int N, int K) {
    int idx = blockIdx.x * blockDim.x + threadIdx.x;
    if (idx >= N * K) return;
    int n = idx % N;
    int k = idx / N;
    out[(size_t)k * N + n] = in[(size_t)n * K + k];
}

// ---------------- transpose + pad: in [Nin,K] -> out [K,64] (pad cols zero) ----
__global__ void wt_transpose_pad64(const float* __restrict__ in, float* __restrict__ out,
                                   int Nin, int K) {
    int idx = blockIdx.x * blockDim.x + threadIdx.x;
    if (idx >= K * 64) return;
    int n = idx % 64;
    int k = idx / 64;
    out[idx] = (n < Nin) ? in[(size_t)n * K + k] : 0.f;
}

// ---------------- layernorm over 384, one block (128 thr) per row ----------------
__global__ __launch_bounds__(128) void ln_kernel(const float* __restrict__ x,
                                                 const float* __restrict__ w,
                                                 const float* __restrict__ b,
                                                 float* __restrict__ out) {
    int m = blockIdx.x;
    int t = threadIdx.x;
    const float* row = x + (size_t)m * 384;
    float v0 = row[t], v1 = row[t + 128], v2 = row[t + 256];
    float s = v0 + v1 + v2;
    __shared__ float red1[4], red2[4];
    #pragma unroll
    for (int o = 16; o; o >>= 1) s += __shfl_xor_sync(0xffffffffu, s, o);
    if ((t & 31) == 0) red1[t >> 5] = s;
    __syncthreads();
    float mu = (red1[0] + red1[1] + red1[2] + red1[3]) * (1.f / 384.f);
    float d0 = v0 - mu, d1 = v1 - mu, d2 = v2 - mu;
    float q = d0 * d0 + d1 * d1 + d2 * d2;
    #pragma unroll
    for (int o = 16; o; o >>= 1) q += __shfl_xor_sync(0xffffffffu, q, o);
    if ((t & 31) == 0) red2[t >> 5] = q;
    __syncthreads();
    float var = (red2[0] + red2[1] + red2[2] + red2[3]) * (1.f / 384.f);
    float inv = rsqrtf(var + 1e-5f);
    float* o = out + (size_t)m * 384;
    o[t]       = d0 * inv * w[t]       + b[t];
    o[t + 128] = d1 * inv * w[t + 128] + b[t + 128];
    o[t + 256] = d2 * inv * w[t + 256] + b[t + 256];
}

// ---------------- SGEMM BK=16, no bounds checks (big GEMMs) ----------------
// C[M,N] = A[M,K] * Bt[K,N] (+bias,+resid). M,N mult of 128, K mult of 16.
// SPLIT: A columns k >= ksplit come from A2 (concat fusion); dead code when false.
template<bool SPLIT>
__global__ __launch_bounds__(256, 2) void sgemm16(
    const float* __restrict__ A, int lda,
    const float* __restrict__ A2, int lda2, int ksplit,
    const float* __restrict__ Bt,
    const float* __restrict__ bias,
    const float* __restrict__ resid, int ldr,
    float* __restrict__ C, int ldc,
    int N, int K)
{
    __shared__ float As[16][132];
    __shared__ float Bs[16][128];
    int tid = threadIdx.x;
    int bm = blockIdx.y * 128, bn = blockIdx.x * 128;
    int row = tid / 16, col = tid % 16;

    float acc[8][8];
    #pragma unroll
    for (int i = 0; i < 8; i++)
        #pragma unroll
        for (int j = 0; j < 8; j++) acc[i][j] = 0.f;

    int a_m = tid >> 1;
    int a_k = (tid & 1) * 8;
    int b_n = (tid & 31) * 4;
    int b_k = tid >> 5;

    const float* ap  = A + (size_t)(bm + a_m) * lda;
    const float* ap2 = SPLIT ? (A2 + (size_t)(bm + a_m) * lda2) : nullptr;
    const float* bp0 = Bt + (size_t)b_k * N + bn + b_n;

    int ktiles = K >> 4;
    for (int t = 0; t < ktiles; ++t) {
        int k0 = t * 16;
        float4 a0, a1;
        if (SPLIT) {
            int gk = k0 + a_k;
            const float* src = (gk >= ksplit) ? (ap2 + (gk - ksplit)) : (ap + gk);
            a0 = *(const float4*)src;
            a1 = *(const float4*)(src + 4);
        } else {
            a0 = *(const float4*)(ap + k0 + a_k);
            a1 = *(const float4*)(ap + k0 + a_k + 4);
        }
        float4 bv0 = *(const float4*)(bp0 + (size_t)k0 * N);
        float4 bv1 = *(const float4*)(bp0 + (size_t)(k0 + 8) * N);
        As[a_k + 0][a_m] = a0.x;
        As[a_k + 1][a_m] = a0.y;
        As[a_k + 2][a_m] = a0.z;
        As[a_k + 3][a_m] = a0.w;
        As[a_k + 4][a_m] = a1.x;
        As[a_k + 5][a_m] = a1.y;
        As[a_k + 6][a_m] = a1.z;
        As[a_k + 7][a_m] = a1.w;
        *(float4*)&Bs[b_k][b_n]     = bv0;
        *(float4*)&Bs[b_k + 8][b_n] = bv1;
        __syncthreads();
        #pragma unroll
        for (int k = 0; k < 16; ++k) {
            float a[8], b[8];
            *(float4*)(a)     = *(const float4*)&As[k][row * 8];
            *(float4*)(a + 4) = *(const float4*)&As[k][row * 8 + 4];
            *(float4*)(b)     = *(const float4*)&Bs[k][col * 8];
            *(float4*)(b + 4) = *(const float4*)&Bs[k][col * 8 + 4];
            #pragma unroll
            for (int i = 0; i < 8; i++)
                #pragma unroll
                for (int j = 0; j < 8; j++)
                    acc[i][j] = fmaf(a[i], b[j], acc[i][j]);
        }
        __syncthreads();
    }
    // epilogue
    #pragma unroll
    for (int i = 0; i < 8; i++) {
        int m = bm + row * 8 + i;
        float* crow = C + (size_t)m * ldc;
        #pragma unroll
        for (int j = 0; j < 8; j += 4) {
            int n0 = bn + col * 8 + j;
            float4 v = make_float4(acc[i][j], acc[i][j + 1], acc[i][j + 2], acc[i][j + 3]);
            if (bias) {
                const float4 bb = *(const float4*)&bias[n0];
                v.x += bb.x; v.y += bb.y; v.z += bb.z; v.w += bb.w;
            }
            if (resid) {
                const float4 rr = *(const float4*)(resid + (size_t)m * ldr + n0);
                v.x += rr.x; v.y += rr.y; v.z += rr.z; v.w += rr.w;
            }
            *(float4*)(crow + n0) = v;
        }
    }
}

// ---------------- SGEMM (round-1 verbatim; used for dt_proj K=24) ----------------
__global__ __launch_bounds__(256) void sgemm(
    const float* __restrict__ A, int lda,
    const float* __restrict__ Bt,
    const float* __restrict__ bias,
    const float* __restrict__ resid, int ldr,
    float* __restrict__ C, int ldc,
    int M, int N, int K, int act)
{
    __shared__ float As[8][132];
    __shared__ float Bs[8][128];
    int tid = threadIdx.x;
    int bm = blockIdx.y * 128, bn = blockIdx.x * 128;
    int row = tid / 16, col = tid % 16;

    float acc[8][8];
    #pragma unroll
    for (int i = 0; i < 8; i++)
        #pragma unroll
        for (int j = 0; j < 8; j++) acc[i][j] = 0.f;

    int a_m = tid / 2;
    int a_k = (tid % 2) * 4;
    int b_n = (tid % 32) * 4;
    int b_k = tid / 32;

    int ktiles = (K + 7) / 8;
    for (int t = 0; t < ktiles; ++t) {
        int k0 = t * 8;
        {
            float4 av = make_float4(0.f, 0.f, 0.f, 0.f);
            int gm = bm + a_m, gk = k0 + a_k;
            const float* ap = A + (size_t)gm * lda;
            if (gk + 3 < K) {
                av = *(const float4*)(ap + gk);
            } else {
                if (gk + 0 < K) av.x = ap[gk + 0];
                if (gk + 1 < K) av.y = ap[gk + 1];
                if (gk + 2 < K) av.z = ap[gk + 2];
                if (gk + 3 < K) av.w = ap[gk + 3];
            }
            As[a_k + 0][a_m] = av.x;
            As[a_k + 1][a_m] = av.y;
            As[a_k + 2][a_m] = av.z;
            As[a_k + 3][a_m] = av.w;
        }
        {
            float4 bv = make_float4(0.f, 0.f, 0.f, 0.f);
            int gn = bn + b_n, gk = k0 + b_k;
            if (gk < K) {
                const float* bp = Bt + (size_t)gk * N;
                if (gn + 3 < N) {
                    bv = *(const float4*)(bp + gn);
                } else {
                    if (gn + 0 < N) bv.x = bp[gn + 0];
                    if (gn + 1 < N) bv.y = bp[gn + 1];
                    if (gn + 2 < N) bv.z = bp[gn + 2];
                    if (gn + 3 < N) bv.w = bp[gn + 3];
                }
            }
            *(float4*)&Bs[b_k][b_n] = bv;
        }
        __syncthreads();
        #pragma unroll
        for (int k = 0; k < 8; ++k) {
            float a[8], b[8];
            *(float4*)(a)     = *(const float4*)&As[k][row * 8];
            *(float4*)(a + 4) = *(const float4*)&As[k][row * 8 + 4];
            *(float4*)(b)     = *(const float4*)&Bs[k][col * 8];
            *(float4*)(b + 4) = *(const float4*)&Bs[k][col * 8 + 4];
            #pragma unroll
            for (int i = 0; i < 8; i++)
                #pragma unroll
                for (int j = 0; j < 8; j++)
                    acc[i][j] = fmaf(a[i], b[j], acc[i][j]);
        }
        __syncthreads();
    }
    #pragma unroll
    for (int i = 0; i < 8; i++) {
        int m = bm + row * 8 + i;
        if (m >= M) continue;
        #pragma unroll
        for (int j = 0; j < 8; j++) {
            int n = bn + col * 8 + j;
            if (n >= N) continue;
            float v = acc[i][j];
            if (bias) v += bias[n];
            if (act == 1) {  // softplus
                v = (v > 20.f) ? v : log1pf(expf(v));
            }
            if (resid) v += resid[(size_t)m * ldr + n];
            C[(size_t)m * ldc + n] = v;
        }
    }
}

// ---------------- narrow SGEMM: tile 128x64, Bt padded [K][64] ----------------
__global__ __launch_bounds__(256) void sgemm64(
    const float* __restrict__ A, int lda,
    const float* __restrict__ Bt,          // [K][64]
    float* __restrict__ C, int ldc,
    int Nstore, int K)
{
    __shared__ float As[8][132];
    __shared__ float Bs[8][64];
    int tid = threadIdx.x;
    int bm = blockIdx.y * 128;
    int row = tid / 16, col = tid % 16;

    float acc[8][4];
    #pragma unroll
    for (int i = 0; i < 8; i++)
        #pragma unroll
        for (int j = 0; j < 4; j++) acc[i][j] = 0.f;

    int a_m = tid / 2;
    int a_k = (tid % 2) * 4;
    int b_k = tid >> 4;
    int b_n = (tid & 15) * 4;

    int ktiles = K / 8;
    for (int t = 0; t < ktiles; ++t) {
        int k0 = t * 8;
        {
            float4 av = *(const float4*)(A + (size_t)(bm + a_m) * lda + k0 + a_k);
            As[a_k + 0][a_m] = av.x;
            As[a_k + 1][a_m] = av.y;
            As[a_k + 2][a_m] = av.z;
            As[a_k + 3][a_m] = av.w;
        }
        if (tid < 128) {
            float4 bv = *(const float4*)(Bt + (size_t)(k0 + b_k) * 64 + b_n);
            *(float4*)&Bs[b_k][b_n] = bv;
        }
        __syncthreads();
        #pragma unroll
        for (int k = 0; k < 8; ++k) {
            float a[8], b[4];
            *(float4*)(a)     = *(const float4*)&As[k][row * 8];
            *(float4*)(a + 4) = *(const float4*)&As[k][row * 8 + 4];
            *(float4*)(b)     = *(const float4*)&Bs[k][col * 4];
            #pragma unroll
            for (int i = 0; i < 8; i++)
                #pragma unroll
                for (int j = 0; j < 4; j++)
                    acc[i][j] = fmaf(a[i], b[j], acc[i][j]);
        }
        __syncthreads();
    }
    #pragma unroll
    for (int i = 0; i < 8; i++) {
        int m = bm + row * 8 + i;
        int n0 = col * 4;
        if (n0 >= Nstore) continue;
        *(float4*)(C + (size_t)m * ldc + n0) =
            make_float4(acc[i][0], acc[i][1], acc[i][2], acc[i][3]);
    }
}

// ---------------- causal depthwise conv1d (K=4) + SiLU ----------------
__global__ void dwconv1d_silu(const float* __restrict__ x, int xstride,
                              const float* __restrict__ w,
                              const float* __restrict__ bias,
                              float* __restrict__ out) {
    int idx = blockIdx.x * blockDim.x + threadIdx.x;
    if (idx >= MROWS * DINNER) return;
    int d = idx % DINNER;
    int m = idx / DINNER;
    int l = m & (LSEQ - 1);
    float acc = bias[d];
    #pragma unroll
    for (int k = 0; k < 4; k++) {
        int ll = l - 3 + k;
        if (ll >= 0)
            acc += w[d * 4 + k] * x[(size_t)(m + (ll - l)) * xstride + d];
    }
    out[(size_t)m * DINNER + d] = silu_f(acc);
}

// ---------------- selective scan (+ fused silu(z) gate) ----------------
__global__ __launch_bounds__(256) void scan_kernel(
    const float* __restrict__ u,
    const float* __restrict__ dt,
    const float* __restrict__ dbl,
    const float* __restrict__ Cm,
    const float* __restrict__ A_log,
    const float* __restrict__ Dp,
    const float* __restrict__ xz,   // z at column offset 768, stride 1536
    float* __restrict__ y)
{
    int b  = blockIdx.x / 48;
    int d0 = (blockIdx.x % 48) * 16;
    int tid = threadIdx.x;
    int dl = tid / 16;
    int n  = tid % 16;
    int d = d0 + dl;
    float a = -expf(A_log[d * 16 + n]);
    float Dv = Dp[d];
    __shared__ float sdt[16][16], su[16][16], sB[16][17], sC[16][17];
    float h = 0.f;
    size_t base = (size_t)b * LSEQ;
    int lo = tid / 16, c = tid % 16;
    for (int l0 = 0; l0 < LSEQ; l0 += 16) {
        size_t m = base + l0 + lo;
        sdt[lo][c] = dt[m * 768 + d0 + c];
        su [lo][c] = u [m * 768 + d0 + c];
        sB [lo][c] = dbl[m * 40 + 24 + c];
        sC [lo][c] = Cm [m * 16 + c];
        __syncthreads();
        #pragma unroll
        for (int s = 0; s < 16; ++s) {
            float dtv = sdt[s][dl];
            float uv  = su [s][dl];
            float Bv  = sB [s][n];
            float Cv  = sC [s][n];
            h = expf(dtv * a) * h + dtv * uv * Bv;
            float p = h * Cv;
            p += __shfl_xor_sync(0xffffffffu, p, 8);
            p += __shfl_xor_sync(0xffffffffu, p, 4);
            p += __shfl_xor_sync(0xffffffffu, p, 2);
            p += __shfl_xor_sync(0xffffffffu, p, 1);
            if (n == 0) {
                size_t mm = base + l0 + s;
                float z = xz[mm * 1536 + 768 + d];
                y[mm * 768 + d] = (p + uv * Dv) * silu_f(z);
            }
        }
        __syncthreads();
    }
}

// ---------------- FUSED (B,L,C)->(B,C,H,W) transpose + 3x3 depthwise conv ----
// Block: (batch b, channel group cg of 32, spatial tile 16x16).
// Loads 18x18 halo x 32 channels from gf (L,C layout) coalesced across c,
// convolves from smem, writes (B,C,H,W) coalesced along w.
__global__ __launch_bounds__(256) void dwconv3x3_fused(
    const float* __restrict__ gf,   // (B, 4096, 384)
    const float* __restrict__ w,    // (384, 9)
    const float* __restrict__ bias,
    float* __restrict__ out)        // (B, 384, 64, 64)
{
    __shared__ float s[32][18 * 18];   // [c][hh*18+ww]
    const int b  = blockIdx.z;
    const int c0 = blockIdx.y * 32;
    const int tileh = (blockIdx.x >> 2) * 16;
    const int tilew = (blockIdx.x & 3) * 16;
    const int tid = threadIdx.x;

    const float* gfb = gf + (size_t)b * 4096 * 384;

    // load 18x18x32 halo, c fastest (coalesced 128B groups)
    for (int i = tid; i < 32 * 324; i += 256) {
        int c  = i & 31;
        int sp = i >> 5;
        int hh = sp / 18, ww = sp - hh * 18;
        int gh = tileh - 1 + hh;
        int gw = tilew - 1 + ww;
        float v = 0.f;
        if (gh >= 0 && gh < 64 && gw >= 0 && gw < 64)
            v = gfb[(size_t)(gh * 64 + gw) * 384 + c0 + c];
        s[c][sp] = v;
    }
    __syncthreads();

    const int wv = tid & 15;
    const int hv = tid >> 4;
    // each thread: 32 channels at spatial (hv, wv)
    #pragma unroll 4
    for (int c = 0; c < 32; ++c) {
        const float* wc = w + (c0 + c) * 9;
        float acc = bias[c0 + c];
        const float* sc = s[c] + hv * 18 + wv;   // top-left of 3x3 window
        acc = fmaf(wc[0], sc[0],        acc);
        acc = fmaf(wc[1], sc[1],        acc);
        acc = fmaf(wc[2], sc[2],        acc);
        acc = fmaf(wc[3], sc[18],       acc);
        acc = fmaf(wc[4], sc[19],       acc);
        acc = fmaf(wc[5], sc[20],       acc);
        acc = fmaf(wc[6], sc[36],       acc);
        acc = fmaf(wc[7], sc[37],       acc);
        acc = fmaf(wc[8], sc[38],       acc);
        out[(((size_t)b * 384 + c0 + c) * 4096) + (tileh + hv) * 64 + tilew + wv] = acc;
    }
}

// ---------------- host ----------------
static void g16(const float* A, int lda, const float* Bt,
                const float* bias, const float* resid, int ldr,
                float* C, int ldc, int N, int K) {
    dim3 grid(N / 128, MROWS / 128);
    sgemm16<false><<<grid, 256>>>(A, lda, nullptr, 0, 0, Bt, bias, resid, ldr,
                                  C, ldc, N, K);
}

extern "C" void kernel_launch(void* const* d_in, const int* in_sizes, int n_in,
                              void* d_out, int out_size) {
    const float* ms          = (const float*)d_in[0];
    const float* pan         = (const float*)d_in[1];
    const float* reduce_W    = (const float*)d_in[2];
    const float* reduce_b    = (const float*)d_in[3];
    const float* ln1_w       = (const float*)d_in[4];
    const float* ln1_b       = (const float*)d_in[5];
    const float* ln2_w       = (const float*)d_in[6];
    const float* ln2_b       = (const float*)d_in[7];
    const float* ln3_w       = (const float*)d_in[8];
    const float* ln3_b       = (const float*)d_in[9];
    const float* in_proj_W   = (const float*)d_in[10];
    const float* in_proj_b_W = (const float*)d_in[11];
    const float* in_proj_c_W = (const float*)d_in[12];
    const float* conv_w      = (const float*)d_in[13];
    const float* conv_bias   = (const float*)d_in[14];
    const float* conv_b_w    = (const float*)d_in[15];
    const float* conv_b_bias = (const float*)d_in[16];
    const float* conv_c_w    = (const float*)d_in[17];
    const float* conv_c_bias = (const float*)d_in[18];
    const float* x_proj_W    = (const float*)d_in[19];
    const float* x_proj_c_W  = (const float*)d_in[20];
    const float* dt_proj_W   = (const float*)d_in[21];
    const float* dt_proj_bias= (const float*)d_in[22];
    const float* A_log       = (const float*)d_in[23];
    const float* Dvec        = (const float*)d_in[24];
    const float* out_proj_W  = (const float*)d_in[25];
    const float* dwconv_w    = (const float*)d_in[26];
    const float* dwconv_b    = (const float*)d_in[27];
    float* out = (float*)d_out;

    float *pWr, *pWin, *pWinb, *pWinc, *pWout, *pWxp64, *pWxpc64, *pWdt;
    float *pmsn, *ppann, *pred, *pconn, *pxz, *pxbp, *pxcp;
    float *px, *pxb, *pxc, *pdbl, *pdt, *pcm, *py, *pgf;
    cudaGetSymbolAddress((void**)&pWr,     g_Wr_t);
    cudaGetSymbolAddress((void**)&pWin,    g_Win_t);
    cudaGetSymbolAddress((void**)&pWinb,   g_Winb_t);
    cudaGetSymbolAddress((void**)&pWinc,   g_Winc_t);
    cudaGetSymbolAddress((void**)&pWout,   g_Wout_t);
    cudaGetSymbolAddress((void**)&pWxp64,  g_Wxp64);
    cudaGetSymbolAddress((void**)&pWxpc64, g_Wxpc64);
    cudaGetSymbolAddress((void**)&pWdt,    g_Wdt_t);
    cudaGetSymbolAddress((void**)&pmsn,    g_msn);
    cudaGetSymbolAddress((void**)&ppann,   g_pann);
    cudaGetSymbolAddress((void**)&pred,    g_red);
    cudaGetSymbolAddress((void**)&pconn,   g_conn);
    cudaGetSymbolAddress((void**)&pxz,     g_xz);
    cudaGetSymbolAddress((void**)&pxbp,    g_xbp);
    cudaGetSymbolAddress((void**)&pxcp,    g_xcp);
    cudaGetSymbolAddress((void**)&px,      g_x);
    cudaGetSymbolAddress((void**)&pxb,     g_xb);
    cudaGetSymbolAddress((void**)&pxc,     g_xc);
    cudaGetSymbolAddress((void**)&pdbl,    g_dbl);
    cudaGetSymbolAddress((void**)&pdt,     g_dt);
    cudaGetSymbolAddress((void**)&pcm,     g_cm);
    cudaGetSymbolAddress((void**)&py,      g_y);
    cudaGetSymbolAddress((void**)&pgf,     g_gf);

    auto wt = [](const float* in, float* o, int N, int K) {
        int tot = N * K;
        wt_transpose<<<(tot + 255) / 256, 256>>>(in, o, N, K);
    };

    // launches 1-5
    wt(reduce_W,  pWr,  384, 768);                          // 1
    wt(in_proj_W, pWin, 1536, 384);                         // 2
    ln_kernel<<<MROWS, 128>>>(ms,  ln1_w, ln1_b, pmsn);     // 3
    ln_kernel<<<MROWS, 128>>>(pan, ln2_w, ln2_b, ppann);    // 4
    wt(in_proj_b_W, pWinb, 768, 384);                       // 5

    // 6: reduce GEMM with fused concat (A = [ms | pan])
    {
        dim3 grid(384 / 128, MROWS / 128);
        sgemm16<true><<<grid, 256>>>(ms, 384, pan, 384, 384, pWr,
                                     reduce_b, nullptr, 0, pred, 384, 384, 768);
    }

    // in_proj GEMM
    g16(pmsn, 384, pWin, nullptr, nullptr, 0, pxz, 1536, 1536, 384);

    ln_kernel<<<MROWS, 128>>>(pred, ln3_w, ln3_b, pconn);

    wt(in_proj_c_W, pWinc, 768, 384);
    wt(dt_proj_W,   pWdt,  768, 24);
    wt(out_proj_W,  pWout, 384, 768);
    wt_transpose_pad64<<<(768 * 64 + 255) / 256, 256>>>(x_proj_W,   pWxp64,  40, 768);
    wt_transpose_pad64<<<(768 * 64 + 255) / 256, 256>>>(x_proj_c_W, pWxpc64, 16, 768);

    g16(ppann, 384, pWinb, nullptr, nullptr, 0, pxbp, 768, 768, 384);
    g16(pconn, 384, pWinc, nullptr, nullptr, 0, pxcp, 768, 768, 384);

    // depthwise causal convs + SiLU
    {
        int tot = MROWS * DINNER;
        int blocks = (tot + 255) / 256;
        dwconv1d_silu<<<blocks, 256>>>(pxz,  1536, conv_w,   conv_bias,   px);
        dwconv1d_silu<<<blocks, 256>>>(pxbp, 768,  conv_b_w, conv_b_bias, pxb);
        dwconv1d_silu<<<blocks, 256>>>(pxcp, 768,  conv_c_w, conv_c_bias, pxc);
    }

    // narrow projections (BN=64 kernel, padded transposed weights)
    sgemm64<<<dim3(1, MROWS / 128), 256>>>(pxb, 768, pWxp64,  pdbl, 40, 40, 768);
    sgemm64<<<dim3(1, MROWS / 128), 256>>>(pxc, 768, pWxpc64, pcm,  16, 16, 768);

    // dt_proj (fp32, K=24, softplus + bias)
    {
        dim3 grid(6, MROWS / 128);
        sgemm<<<grid, 256>>>(pdbl, 40, pWdt, dt_proj_bias, nullptr, 0,
                             pdt, 768, MROWS, 768, 24, 1);
    }

    // selective scan with fused silu(z) gate
    scan_kernel<<<BSZ * 48, 256>>>(px, pdt, pdbl, pcm, A_log, Dvec, pxz, py);

    // out_proj + residual(ms)
    g16(py, 768, pWout, nullptr, ms, 384, pgf, 384, 384, 768);

    // fused (B,L,C)->(B,C,H,W) transpose + 3x3 depthwise conv
    {
        dim3 grid(16, DIMC / 32, BSZ);   // 4x4 spatial tiles, 12 channel groups, 4 batches
        dwconv3x3_fused<<<grid, 256>>>(pgf, dwconv_w, dwconv_b, out);
    }
}

// round 14
// speedup vs baseline: 1.4070x; 1.4070x over previous
#include <cuda_runtime.h>
#include <math.h>
#include <stdint.h>

#define MROWS  16384
#define LSEQ   4096
#define BSZ    4
#define DIMC   384
#define DINNER 768
#define DSTATE 16
#define DTRANK 24

// ---------------- scratch (device globals; allocation-free) ----------------
__device__ float g_Wr_t  [768*384];    // reduce_W^T   (K=768, N=384)
__device__ float g_Win_t [384*1536];   // in_proj_W^T
__device__ float g_Winb_t[384*768];
__device__ float g_Winc_t[384*768];
__device__ float g_Wout_t[768*384];
__device__ float g_Wxp64 [768*64];     // x_proj_W^T padded  [768][64]
__device__ float g_Wxpc64[768*64];     // x_proj_c_W^T padded [768][64]
__device__ float g_Wdt_t [24*768];

__device__ float g_msn   [MROWS*384];
__device__ float g_pann  [MROWS*384];
__device__ float g_red   [MROWS*384];
__device__ float g_conn  [MROWS*384];
__device__ float g_xz    [(size_t)MROWS*1536];
__device__ float g_xbp   [MROWS*768];
__device__ float g_xcp   [MROWS*768];
__device__ float g_x     [MROWS*768];
__device__ float g_xb    [MROWS*768];
__device__ float g_xc    [MROWS*768];
__device__ float g_dbl   [MROWS*40];
__device__ float g_dt    [MROWS*768];
__device__ float g_cm    [MROWS*16];
__device__ float g_y     [MROWS*768];
__device__ float g_gf    [MROWS*384];
__device__ float g_img   [MROWS*384];

// ---------------- helpers ----------------
__device__ __forceinline__ float silu_f(float v) {
    return v / (1.f + __expf(-v));
}

// ---------------- weight transpose: out[k*N+n] = in[n*K+k] ----------------
__global__ void wt_transpose(const float* __restrict__ in, float* __restrict__ out,
                             int N, int K) {
    int idx = blockIdx.x * blockDim.x + threadIdx.x;
    if (idx >= N * K) return;
    int n = idx % N;
    int k = idx / N;
    out[(size_t)k * N + n] = in[(size_t)n * K + k];
}

// ---------------- transpose + pad: in [Nin,K] -> out [K,64] (pad cols zero) ----
__global__ void wt_transpose_pad64(const float* __restrict__ in, float* __restrict__ out,
                                   int Nin, int K) {
    int idx = blockIdx.x * blockDim.x + threadIdx.x;
    if (idx >= K * 64) return;
    int n = idx % 64;
    int k = idx / 64;
    out[idx] = (n < Nin) ? in[(size_t)n * K + k] : 0.f;
}

// ---------------- layernorm over 384, one block (128 thr) per row ----------------
__global__ __launch_bounds__(128) void ln_kernel(const float* __restrict__ x,
                                                 const float* __restrict__ w,
                                                 const float* __restrict__ b,
                                                 float* __restrict__ out) {
    int m = blockIdx.x;
    int t = threadIdx.x;
    const float* row = x + (size_t)m * 384;
    float v0 = row[t], v1 = row[t + 128], v2 = row[t + 256];
    float s = v0 + v1 + v2;
    __shared__ float red1[4], red2[4];
    #pragma unroll
    for (int o = 16; o; o >>= 1) s += __shfl_xor_sync(0xffffffffu, s, o);
    if ((t & 31) == 0) red1[t >> 5] = s;
    __syncthreads();
    float mu = (red1[0] + red1[1] + red1[2] + red1[3]) * (1.f / 384.f);
    float d0 = v0 - mu, d1 = v1 - mu, d2 = v2 - mu;
    float q = d0 * d0 + d1 * d1 + d2 * d2;
    #pragma unroll
    for (int o = 16; o; o >>= 1) q += __shfl_xor_sync(0xffffffffu, q, o);
    if ((t & 31) == 0) red2[t >> 5] = q;
    __syncthreads();
    float var = (red2[0] + red2[1] + red2[2] + red2[3]) * (1.f / 384.f);
    float inv = rsqrtf(var + 1e-5f);
    float* o = out + (size_t)m * 384;
    o[t]       = d0 * inv * w[t]       + b[t];
    o[t + 128] = d1 * inv * w[t + 128] + b[t + 128];
    o[t + 256] = d2 * inv * w[t + 256] + b[t + 256];
}

// ---------------- SGEMM BK=16, no bounds checks (big GEMMs) ----------------
// C[M,N] = A[M,K] * Bt[K,N] (+bias,+resid). M,N mult of 128, K mult of 16.
// SPLIT: A columns k >= ksplit come from A2 (concat fusion); dead code when false.
template<bool SPLIT>
__global__ __launch_bounds__(256, 2) void sgemm16(
    const float* __restrict__ A, int lda,
    const float* __restrict__ A2, int lda2, int ksplit,
    const float* __restrict__ Bt,
    const float* __restrict__ bias,
    const float* __restrict__ resid, int ldr,
    float* __restrict__ C, int ldc,
    int N, int K)
{
    __shared__ float As[16][132];
    __shared__ float Bs[16][128];
    int tid = threadIdx.x;
    int bm = blockIdx.y * 128, bn = blockIdx.x * 128;
    int row = tid / 16, col = tid % 16;

    float acc[8][8];
    #pragma unroll
    for (int i = 0; i < 8; i++)
        #pragma unroll
        for (int j = 0; j < 8; j++) acc[i][j] = 0.f;

    int a_m = tid >> 1;
    int a_k = (tid & 1) * 8;
    int b_n = (tid & 31) * 4;
    int b_k = tid >> 5;

    const float* ap  = A + (size_t)(bm + a_m) * lda;
    const float* ap2 = SPLIT ? (A2 + (size_t)(bm + a_m) * lda2) : nullptr;
    const float* bp0 = Bt + (size_t)b_k * N + bn + b_n;

    int ktiles = K >> 4;
    for (int t = 0; t < ktiles; ++t) {
        int k0 = t * 16;
        float4 a0, a1;
        if (SPLIT) {
            int gk = k0 + a_k;
            const float* src = (gk >= ksplit) ? (ap2 + (gk - ksplit)) : (ap + gk);
            a0 = *(const float4*)src;
            a1 = *(const float4*)(src + 4);
        } else {
            a0 = *(const float4*)(ap + k0 + a_k);
            a1 = *(const float4*)(ap + k0 + a_k + 4);
        }
        float4 bv0 = *(const float4*)(bp0 + (size_t)k0 * N);
        float4 bv1 = *(const float4*)(bp0 + (size_t)(k0 + 8) * N);
        As[a_k + 0][a_m] = a0.x;
        As[a_k + 1][a_m] = a0.y;
        As[a_k + 2][a_m] = a0.z;
        As[a_k + 3][a_m] = a0.w;
        As[a_k + 4][a_m] = a1.x;
        As[a_k + 5][a_m] = a1.y;
        As[a_k + 6][a_m] = a1.z;
        As[a_k + 7][a_m] = a1.w;
        *(float4*)&Bs[b_k][b_n]     = bv0;
        *(float4*)&Bs[b_k + 8][b_n] = bv1;
        __syncthreads();
        #pragma unroll
        for (int k = 0; k < 16; ++k) {
            float a[8], b[8];
            *(float4*)(a)     = *(const float4*)&As[k][row * 8];
            *(float4*)(a + 4) = *(const float4*)&As[k][row * 8 + 4];
            *(float4*)(b)     = *(const float4*)&Bs[k][col * 8];
            *(float4*)(b + 4) = *(const float4*)&Bs[k][col * 8 + 4];
            #pragma unroll
            for (int i = 0; i < 8; i++)
                #pragma unroll
                for (int j = 0; j < 8; j++)
                    acc[i][j] = fmaf(a[i], b[j], acc[i][j]);
        }
        __syncthreads();
    }
    // epilogue
    #pragma unroll
    for (int i = 0; i < 8; i++) {
        int m = bm + row * 8 + i;
        float* crow = C + (size_t)m * ldc;
        #pragma unroll
        for (int j = 0; j < 8; j += 4) {
            int n0 = bn + col * 8 + j;
            float4 v = make_float4(acc[i][j], acc[i][j + 1], acc[i][j + 2], acc[i][j + 3]);
            if (bias) {
                const float4 bb = *(const float4*)&bias[n0];
                v.x += bb.x; v.y += bb.y; v.z += bb.z; v.w += bb.w;
            }
            if (resid) {
                const float4 rr = *(const float4*)(resid + (size_t)m * ldr + n0);
                v.x += rr.x; v.y += rr.y; v.z += rr.z; v.w += rr.w;
            }
            *(float4*)(crow + n0) = v;
        }
    }
}

// ---------------- SGEMM (round-1 verbatim; used for dt_proj K=24) ----------------
__global__ __launch_bounds__(256) void sgemm(
    const float* __restrict__ A, int lda,
    const float* __restrict__ Bt,
    const float* __restrict__ bias,
    const float* __restrict__ resid, int ldr,
    float* __restrict__ C, int ldc,
    int M, int N, int K, int act)
{
    __shared__ float As[8][132];
    __shared__ float Bs[8][128];
    int tid = threadIdx.x;
    int bm = blockIdx.y * 128, bn = blockIdx.x * 128;
    int row = tid / 16, col = tid % 16;

    float acc[8][8];
    #pragma unroll
    for (int i = 0; i < 8; i++)
        #pragma unroll
        for (int j = 0; j < 8; j++) acc[i][j] = 0.f;

    int a_m = tid / 2;
    int a_k = (tid % 2) * 4;
    int b_n = (tid % 32) * 4;
    int b_k = tid / 32;

    int ktiles = (K + 7) / 8;
    for (int t = 0; t < ktiles; ++t) {
        int k0 = t * 8;
        {
            float4 av = make_float4(0.f, 0.f, 0.f, 0.f);
            int gm = bm + a_m, gk = k0 + a_k;
            const float* ap = A + (size_t)gm * lda;
            if (gk + 3 < K) {
                av = *(const float4*)(ap + gk);
            } else {
                if (gk + 0 < K) av.x = ap[gk + 0];
                if (gk + 1 < K) av.y = ap[gk + 1];
                if (gk + 2 < K) av.z = ap[gk + 2];
                if (gk + 3 < K) av.w = ap[gk + 3];
            }
            As[a_k + 0][a_m] = av.x;
            As[a_k + 1][a_m] = av.y;
            As[a_k + 2][a_m] = av.z;
            As[a_k + 3][a_m] = av.w;
        }
        {
            float4 bv = make_float4(0.f, 0.f, 0.f, 0.f);
            int gn = bn + b_n, gk = k0 + b_k;
            if (gk < K) {
                const float* bp = Bt + (size_t)gk * N;
                if (gn + 3 < N) {
                    bv = *(const float4*)(bp + gn);
                } else {
                    if (gn + 0 < N) bv.x = bp[gn + 0];
                    if (gn + 1 < N) bv.y = bp[gn + 1];
                    if (gn + 2 < N) bv.z = bp[gn + 2];
                    if (gn + 3 < N) bv.w = bp[gn + 3];
                }
            }
            *(float4*)&Bs[b_k][b_n] = bv;
        }
        __syncthreads();
        #pragma unroll
        for (int k = 0; k < 8; ++k) {
            float a[8], b[8];
            *(float4*)(a)     = *(const float4*)&As[k][row * 8];
            *(float4*)(a + 4) = *(const float4*)&As[k][row * 8 + 4];
            *(float4*)(b)     = *(const float4*)&Bs[k][col * 8];
            *(float4*)(b + 4) = *(const float4*)&Bs[k][col * 8 + 4];
            #pragma unroll
            for (int i = 0; i < 8; i++)
                #pragma unroll
                for (int j = 0; j < 8; j++)
                    acc[i][j] = fmaf(a[i], b[j], acc[i][j]);
        }
        __syncthreads();
    }
    #pragma unroll
    for (int i = 0; i < 8; i++) {
        int m = bm + row * 8 + i;
        if (m >= M) continue;
        #pragma unroll
        for (int j = 0; j < 8; j++) {
            int n = bn + col * 8 + j;
            if (n >= N) continue;
            float v = acc[i][j];
            if (bias) v += bias[n];
            if (act == 1) {  // softplus
                v = (v > 20.f) ? v : log1pf(expf(v));
            }
            if (resid) v += resid[(size_t)m * ldr + n];
            C[(size_t)m * ldc + n] = v;
        }
    }
}

// ---------------- narrow SGEMM: tile 128x64, Bt padded [K][64] ----------------
__global__ __launch_bounds__(256) void sgemm64(
    const float* __restrict__ A, int lda,
    const float* __restrict__ Bt,          // [K][64]
    float* __restrict__ C, int ldc,
    int Nstore, int K)
{
    __shared__ float As[8][132];
    __shared__ float Bs[8][64];
    int tid = threadIdx.x;
    int bm = blockIdx.y * 128;
    int row = tid / 16, col = tid % 16;

    float acc[8][4];
    #pragma unroll
    for (int i = 0; i < 8; i++)
        #pragma unroll
        for (int j = 0; j < 4; j++) acc[i][j] = 0.f;

    int a_m = tid / 2;
    int a_k = (tid % 2) * 4;
    int b_k = tid >> 4;
    int b_n = (tid & 15) * 4;

    int ktiles = K / 8;
    for (int t = 0; t < ktiles; ++t) {
        int k0 = t * 8;
        {
            float4 av = *(const float4*)(A + (size_t)(bm + a_m) * lda + k0 + a_k);
            As[a_k + 0][a_m] = av.x;
            As[a_k + 1][a_m] = av.y;
            As[a_k + 2][a_m] = av.z;
            As[a_k + 3][a_m] = av.w;
        }
        if (tid < 128) {
            float4 bv = *(const float4*)(Bt + (size_t)(k0 + b_k) * 64 + b_n);
            *(float4*)&Bs[b_k][b_n] = bv;
        }
        __syncthreads();
        #pragma unroll
        for (int k = 0; k < 8; ++k) {
            float a[8], b[4];
            *(float4*)(a)     = *(const float4*)&As[k][row * 8];
            *(float4*)(a + 4) = *(const float4*)&As[k][row * 8 + 4];
            *(float4*)(b)     = *(const float4*)&Bs[k][col * 4];
            #pragma unroll
            for (int i = 0; i < 8; i++)
                #pragma unroll
                for (int j = 0; j < 4; j++)
                    acc[i][j] = fmaf(a[i], b[j], acc[i][j]);
        }
        __syncthreads();
    }
    #pragma unroll
    for (int i = 0; i < 8; i++) {
        int m = bm + row * 8 + i;
        int n0 = col * 4;
        if (n0 >= Nstore) continue;
        *(float4*)(C + (size_t)m * ldc + n0) =
            make_float4(acc[i][0], acc[i][1], acc[i][2], acc[i][3]);
    }
}

// ---------------- causal depthwise conv1d (K=4) + SiLU ----------------
__global__ void dwconv1d_silu(const float* __restrict__ x, int xstride,
                              const float* __restrict__ w,
                              const float* __restrict__ bias,
                              float* __restrict__ out) {
    int idx = blockIdx.x * blockDim.x + threadIdx.x;
    if (idx >= MROWS * DINNER) return;
    int d = idx % DINNER;
    int m = idx / DINNER;
    int l = m & (LSEQ - 1);
    float acc = bias[d];
    #pragma unroll
    for (int k = 0; k < 4; k++) {
        int ll = l - 3 + k;
        if (ll >= 0)
            acc += w[d * 4 + k] * x[(size_t)(m + (ll - l)) * xstride + d];
    }
    out[(size_t)m * DINNER + d] = silu_f(acc);
}

// ---------------- selective scan (+ fused silu(z) gate) ----------------
__global__ __launch_bounds__(256) void scan_kernel(
    const float* __restrict__ u,
    const float* __restrict__ dt,
    const float* __restrict__ dbl,
    const float* __restrict__ Cm,
    const float* __restrict__ A_log,
    const float* __restrict__ Dp,
    const float* __restrict__ xz,   // z at column offset 768, stride 1536
    float* __restrict__ y)
{
    int b  = blockIdx.x / 48;
    int d0 = (blockIdx.x % 48) * 16;
    int tid = threadIdx.x;
    int dl = tid / 16;
    int n  = tid % 16;
    int d = d0 + dl;
    float a = -expf(A_log[d * 16 + n]);
    float Dv = Dp[d];
    __shared__ float sdt[16][16], su[16][16], sB[16][17], sC[16][17];
    float h = 0.f;
    size_t base = (size_t)b * LSEQ;
    int lo = tid / 16, c = tid % 16;
    for (int l0 = 0; l0 < LSEQ; l0 += 16) {
        size_t m = base + l0 + lo;
        sdt[lo][c] = dt[m * 768 + d0 + c];
        su [lo][c] = u [m * 768 + d0 + c];
        sB [lo][c] = dbl[m * 40 + 24 + c];
        sC [lo][c] = Cm [m * 16 + c];
        __syncthreads();
        #pragma unroll
        for (int s = 0; s < 16; ++s) {
            float dtv = sdt[s][dl];
            float uv  = su [s][dl];
            float Bv  = sB [s][n];
            float Cv  = sC [s][n];
            h = expf(dtv * a) * h + dtv * uv * Bv;
            float p = h * Cv;
            p += __shfl_xor_sync(0xffffffffu, p, 8);
            p += __shfl_xor_sync(0xffffffffu, p, 4);
            p += __shfl_xor_sync(0xffffffffu, p, 2);
            p += __shfl_xor_sync(0xffffffffu, p, 1);
            if (n == 0) {
                size_t mm = base + l0 + s;
                float z = xz[mm * 1536 + 768 + d];
                y[mm * 768 + d] = (p + uv * Dv) * silu_f(z);
            }
        }
        __syncthreads();
    }
}

// ---------------- (B,L,C) -> (B,C,L) transpose ----------------
__global__ void transpose_LC(const float* __restrict__ in, float* __restrict__ out) {
    __shared__ float t[32][33];
    int bb = blockIdx.z;
    int c0 = blockIdx.x * 32, l0 = blockIdx.y * 32;
    const float* ip = in + (size_t)bb * LSEQ * DIMC;
    float* op = out + (size_t)bb * DIMC * LSEQ;
    int tx = threadIdx.x, ty = threadIdx.y;
    #pragma unroll
    for (int i = 0; i < 32; i += 8)
        t[ty + i][tx] = ip[(size_t)(l0 + ty + i) * DIMC + c0 + tx];
    __syncthreads();
    #pragma unroll
    for (int i = 0; i < 32; i += 8)
        op[(size_t)(c0 + ty + i) * LSEQ + l0 + tx] = t[tx][ty + i];
}

// ---------------- final 3x3 depthwise conv (SAME) on (B,C,64,64) ----------------
__global__ void dwconv3x3(const float* __restrict__ img, const float* __restrict__ w,
                          const float* __restrict__ bias, float* __restrict__ out) {
    int idx = blockIdx.x * blockDim.x + threadIdx.x;
    if (idx >= BSZ * DIMC * 64 * 64) return;
    int wv = idx & 63;
    int h  = (idx >> 6) & 63;
    int c  = (idx >> 12) % DIMC;
    int b  = idx / (DIMC * 4096);
    const float* ip = img + ((size_t)b * DIMC + c) * 4096;
    const float* wc = w + c * 9;
    float acc = bias[c];
    #pragma unroll
    for (int dh = -1; dh <= 1; dh++) {
        int hh = h + dh;
        if (hh < 0 || hh >= 64) continue;
        #pragma unroll
        for (int dw = -1; dw <= 1; dw++) {
            int ww = wv + dw;
            if (ww < 0 || ww >= 64) continue;
            acc += wc[(dh + 1) * 3 + (dw + 1)] * ip[hh * 64 + ww];
        }
    }
    out[idx] = acc;
}

// ---------------- host ----------------
static void g16(const float* A, int lda, const float* Bt,
                const float* bias, const float* resid, int ldr,
                float* C, int ldc, int N, int K) {
    dim3 grid(N / 128, MROWS / 128);
    sgemm16<false><<<grid, 256>>>(A, lda, nullptr, 0, 0, Bt, bias, resid, ldr,
                                  C, ldc, N, K);
}

extern "C" void kernel_launch(void* const* d_in, const int* in_sizes, int n_in,
                              void* d_out, int out_size) {
    const float* ms          = (const float*)d_in[0];
    const float* pan         = (const float*)d_in[1];
    const float* reduce_W    = (const float*)d_in[2];
    const float* reduce_b    = (const float*)d_in[3];
    const float* ln1_w       = (const float*)d_in[4];
    const float* ln1_b       = (const float*)d_in[5];
    const float* ln2_w       = (const float*)d_in[6];
    const float* ln2_b       = (const float*)d_in[7];
    const float* ln3_w       = (const float*)d_in[8];
    const float* ln3_b       = (const float*)d_in[9];
    const float* in_proj_W   = (const float*)d_in[10];
    const float* in_proj_b_W = (const float*)d_in[11];
    const float* in_proj_c_W = (const float*)d_in[12];
    const float* conv_w      = (const float*)d_in[13];
    const float* conv_bias   = (const float*)d_in[14];
    const float* conv_b_w    = (const float*)d_in[15];
    const float* conv_b_bias = (const float*)d_in[16];
    const float* conv_c_w    = (const float*)d_in[17];
    const float* conv_c_bias = (const float*)d_in[18];
    const float* x_proj_W    = (const float*)d_in[19];
    const float* x_proj_c_W  = (const float*)d_in[20];
    const float* dt_proj_W   = (const float*)d_in[21];
    const float* dt_proj_bias= (const float*)d_in[22];
    const float* A_log       = (const float*)d_in[23];
    const float* Dvec        = (const float*)d_in[24];
    const float* out_proj_W  = (const float*)d_in[25];
    const float* dwconv_w    = (const float*)d_in[26];
    const float* dwconv_b    = (const float*)d_in[27];
    float* out = (float*)d_out;

    float *pWr, *pWin, *pWinb, *pWinc, *pWout, *pWxp64, *pWxpc64, *pWdt;
    float *pmsn, *ppann, *pred, *pconn, *pxz, *pxbp, *pxcp;
    float *px, *pxb, *pxc, *pdbl, *pdt, *pcm, *py, *pgf, *pimg;
    cudaGetSymbolAddress((void**)&pWr,     g_Wr_t);
    cudaGetSymbolAddress((void**)&pWin,    g_Win_t);
    cudaGetSymbolAddress((void**)&pWinb,   g_Winb_t);
    cudaGetSymbolAddress((void**)&pWinc,   g_Winc_t);
    cudaGetSymbolAddress((void**)&pWout,   g_Wout_t);
    cudaGetSymbolAddress((void**)&pWxp64,  g_Wxp64);
    cudaGetSymbolAddress((void**)&pWxpc64, g_Wxpc64);
    cudaGetSymbolAddress((void**)&pWdt,    g_Wdt_t);
    cudaGetSymbolAddress((void**)&pmsn,    g_msn);
    cudaGetSymbolAddress((void**)&ppann,   g_pann);
    cudaGetSymbolAddress((void**)&pred,    g_red);
    cudaGetSymbolAddress((void**)&pconn,   g_conn);
    cudaGetSymbolAddress((void**)&pxz,     g_xz);
    cudaGetSymbolAddress((void**)&pxbp,    g_xbp);
    cudaGetSymbolAddress((void**)&pxcp,    g_xcp);
    cudaGetSymbolAddress((void**)&px,      g_x);
    cudaGetSymbolAddress((void**)&pxb,     g_xb);
    cudaGetSymbolAddress((void**)&pxc,     g_xc);
    cudaGetSymbolAddress((void**)&pdbl,    g_dbl);
    cudaGetSymbolAddress((void**)&pdt,     g_dt);
    cudaGetSymbolAddress((void**)&pcm,     g_cm);
    cudaGetSymbolAddress((void**)&py,      g_y);
    cudaGetSymbolAddress((void**)&pgf,     g_gf);
    cudaGetSymbolAddress((void**)&pimg,    g_img);

    auto wt = [](const float* in, float* o, int N, int K) {
        int tot = N * K;
        wt_transpose<<<(tot + 255) / 256, 256>>>(in, o, N, K);
    };

    // launches 1-5
    wt(reduce_W,  pWr,  384, 768);                          // 1
    wt(in_proj_W, pWin, 1536, 384);                         // 2
    ln_kernel<<<MROWS, 128>>>(ms,  ln1_w, ln1_b, pmsn);     // 3
    ln_kernel<<<MROWS, 128>>>(pan, ln2_w, ln2_b, ppann);    // 4
    wt(in_proj_b_W, pWinb, 768, 384);                       // 5

    // 6: reduce GEMM with fused concat (A = [ms | pan])
    {
        dim3 grid(384 / 128, MROWS / 128);
        sgemm16<true><<<grid, 256>>>(ms, 384, pan, 384, 384, pWr,
                                     reduce_b, nullptr, 0, pred, 384, 384, 768);
    }

    // in_proj GEMM
    g16(pmsn, 384, pWin, nullptr, nullptr, 0, pxz, 1536, 1536, 384);

    ln_kernel<<<MROWS, 128>>>(pred, ln3_w, ln3_b, pconn);

    wt(in_proj_c_W, pWinc, 768, 384);
    wt(dt_proj_W,   pWdt,  768, 24);
    wt(out_proj_W,  pWout, 384, 768);
    wt_transpose_pad64<<<(768 * 64 + 255) / 256, 256>>>(x_proj_W,   pWxp64,  40, 768);
    wt_transpose_pad64<<<(768 * 64 + 255) / 256, 256>>>(x_proj_c_W, pWxpc64, 16, 768);

    g16(ppann, 384, pWinb, nullptr, nullptr, 0, pxbp, 768, 768, 384);
    g16(pconn, 384, pWinc, nullptr, nullptr, 0, pxcp, 768, 768, 384);

    // depthwise causal convs + SiLU
    {
        int tot = MROWS * DINNER;
        int blocks = (tot + 255) / 256;
        dwconv1d_silu<<<blocks, 256>>>(pxz,  1536, conv_w,   conv_bias,   px);
        dwconv1d_silu<<<blocks, 256>>>(pxbp, 768,  conv_b_w, conv_b_bias, pxb);
        dwconv1d_silu<<<blocks, 256>>>(pxcp, 768,  conv_c_w, conv_c_bias, pxc);
    }

    // narrow projections (BN=64 kernel, padded transposed weights)
    sgemm64<<<dim3(1, MROWS / 128), 256>>>(pxb, 768, pWxp64,  pdbl, 40, 40, 768);
    sgemm64<<<dim3(1, MROWS / 128), 256>>>(pxc, 768, pWxpc64, pcm,  16, 16, 768);

    // dt_proj (fp32, K=24, softplus + bias) — round-1 bounds-checked kernel
    {
        dim3 grid(6, MROWS / 128);
        sgemm<<<grid, 256>>>(pdbl, 40, pWdt, dt_proj_bias, nullptr, 0,
                             pdt, 768, MROWS, 768, 24, 1);
    }

    // selective scan with fused silu(z) gate
    scan_kernel<<<BSZ * 48, 256>>>(px, pdt, pdbl, pcm, A_log, Dvec, pxz, py);

    // out_proj + residual(ms)
    g16(py, 768, pWout, nullptr, ms, 384, pgf, 384, 384, 768);

    // (B,L,C) -> (B,C,HW) transpose, then 3x3 depthwise conv
    {
        dim3 grid(DIMC / 32, LSEQ / 32, BSZ);
        dim3 blk(32, 8);
        transpose_LC<<<grid, blk>>>(pgf, pimg);
    }
    {
        int tot = BSZ * DIMC * 64 * 64;
        dwconv3x3<<<(tot + 255) / 256, 256>>>(pimg, dwconv_w, dwconv_b, out);
    }
}

// round 15
// speedup vs baseline: 2.2243x; 1.5809x over previous
#include <cuda_runtime.h>
#include <math.h>
#include <stdint.h>

#define MROWS  16384
#define LSEQ   4096
#define BSZ    4
#define DIMC   384
#define DINNER 768
#define DSTATE 16
#define DTRANK 24

// ---------------- scratch (device globals; allocation-free) ----------------
__device__ float g_Wr_t  [768*384];    // reduce_W^T   (K=768, N=384)
__device__ float g_Win_t [384*1536];   // in_proj_W^T
__device__ float g_Winb_t[384*768];
__device__ float g_Winc_t[384*768];
__device__ float g_Wout_t[768*384];
__device__ float g_Wxp64 [768*64];     // x_proj_W^T padded  [768][64]
__device__ float g_Wxpc64[768*64];     // x_proj_c_W^T padded [768][64]
__device__ float g_Wdt_t [24*768];

__device__ float g_msn   [MROWS*384];
__device__ float g_pann  [MROWS*384];
__device__ float g_red   [MROWS*384];
__device__ float g_conn  [MROWS*384];
__device__ float g_xz    [(size_t)MROWS*1536];
__device__ float g_xbp   [MROWS*768];
__device__ float g_xcp   [MROWS*768];
__device__ float g_x     [MROWS*768];
__device__ float g_xb    [MROWS*768];
__device__ float g_xc    [MROWS*768];
__device__ float g_dbl   [MROWS*40];
__device__ float g_dt    [MROWS*768];
__device__ float g_cm    [MROWS*16];
__device__ float g_y     [MROWS*768];
__device__ float g_gf    [MROWS*384];
__device__ float g_img   [MROWS*384];

// ---------------- helpers ----------------
__device__ __forceinline__ float silu_f(float v) {
    return v / (1.f + __expf(-v));
}

// ---------------- weight transpose: out[k*N+n] = in[n*K+k] ----------------
__global__ void wt_transpose(const float* __restrict__ in, float* __restrict__ out,
                             int N, int K) {
    int idx = blockIdx.x * blockDim.x + threadIdx.x;
    if (idx >= N * K) return;
    int n = idx % N;
    int k = idx / N;
    out[(size_t)k * N + n] = in[(size_t)n * K + k];
}

// ---------------- transpose + pad: in [Nin,K] -> out [K,64] (pad cols zero) ----
__global__ void wt_transpose_pad64(const float* __restrict__ in, float* __restrict__ out,
                                   int Nin, int K) {
    int idx = blockIdx.x * blockDim.x + threadIdx.x;
    if (idx >= K * 64) return;
    int n = idx % 64;
    int k = idx / 64;
    out[idx] = (n < Nin) ? in[(size_t)n * K + k] : 0.f;
}

// ---------------- layernorm over 384, one block (128 thr) per row ----------------
__global__ __launch_bounds__(128) void ln_kernel(const float* __restrict__ x,
                                                 const float* __restrict__ w,
                                                 const float* __restrict__ b,
                                                 float* __restrict__ out) {
    int m = blockIdx.x;
    int t = threadIdx.x;
    const float* row = x + (size_t)m * 384;
    float v0 = row[t], v1 = row[t + 128], v2 = row[t + 256];
    float s = v0 + v1 + v2;
    __shared__ float red1[4], red2[4];
    #pragma unroll
    for (int o = 16; o; o >>= 1) s += __shfl_xor_sync(0xffffffffu, s, o);
    if ((t & 31) == 0) red1[t >> 5] = s;
    __syncthreads();
    float mu = (red1[0] + red1[1] + red1[2] + red1[3]) * (1.f / 384.f);
    float d0 = v0 - mu, d1 = v1 - mu, d2 = v2 - mu;
    float q = d0 * d0 + d1 * d1 + d2 * d2;
    #pragma unroll
    for (int o = 16; o; o >>= 1) q += __shfl_xor_sync(0xffffffffu, q, o);
    if ((t & 31) == 0) red2[t >> 5] = q;
    __syncthreads();
    float var = (red2[0] + red2[1] + red2[2] + red2[3]) * (1.f / 384.f);
    float inv = rsqrtf(var + 1e-5f);
    float* o = out + (size_t)m * 384;
    o[t]       = d0 * inv * w[t]       + b[t];
    o[t + 128] = d1 * inv * w[t + 128] + b[t + 128];
    o[t + 256] = d2 * inv * w[t + 256] + b[t + 256];
}

// ---------------- SGEMM BK=16, no bounds checks (big GEMMs) ----------------
// C[M,N] = A[M,K] * Bt[K,N] (+bias,+resid). M,N mult of 128, K mult of 16.
// SPLIT: A columns k >= ksplit come from A2 (concat fusion); dead code when false.
template<bool SPLIT>
__global__ __launch_bounds__(256, 2) void sgemm16(
    const float* __restrict__ A, int lda,
    const float* __restrict__ A2, int lda2, int ksplit,
    const float* __restrict__ Bt,
    const float* __restrict__ bias,
    const float* __restrict__ resid, int ldr,
    float* __restrict__ C, int ldc,
    int N, int K)
{
    __shared__ float As[16][132];
    __shared__ float Bs[16][128];
    int tid = threadIdx.x;
    int bm = blockIdx.y * 128, bn = blockIdx.x * 128;
    int row = tid / 16, col = tid % 16;

    float acc[8][8];
    #pragma unroll
    for (int i = 0; i < 8; i++)
        #pragma unroll
        for (int j = 0; j < 8; j++) acc[i][j] = 0.f;

    int a_m = tid >> 1;
    int a_k = (tid & 1) * 8;
    int b_n = (tid & 31) * 4;
    int b_k = tid >> 5;

    const float* ap  = A + (size_t)(bm + a_m) * lda;
    const float* ap2 = SPLIT ? (A2 + (size_t)(bm + a_m) * lda2) : nullptr;
    const float* bp0 = Bt + (size_t)b_k * N + bn + b_n;

    int ktiles = K >> 4;
    for (int t = 0; t < ktiles; ++t) {
        int k0 = t * 16;
        float4 a0, a1;
        if (SPLIT) {
            int gk = k0 + a_k;
            const float* src = (gk >= ksplit) ? (ap2 + (gk - ksplit)) : (ap + gk);
            a0 = *(const float4*)src;
            a1 = *(const float4*)(src + 4);
        } else {
            a0 = *(const float4*)(ap + k0 + a_k);
            a1 = *(const float4*)(ap + k0 + a_k + 4);
        }
        float4 bv0 = *(const float4*)(bp0 + (size_t)k0 * N);
        float4 bv1 = *(const float4*)(bp0 + (size_t)(k0 + 8) * N);
        As[a_k + 0][a_m] = a0.x;
        As[a_k + 1][a_m] = a0.y;
        As[a_k + 2][a_m] = a0.z;
        As[a_k + 3][a_m] = a0.w;
        As[a_k + 4][a_m] = a1.x;
        As[a_k + 5][a_m] = a1.y;
        As[a_k + 6][a_m] = a1.z;
        As[a_k + 7][a_m] = a1.w;
        *(float4*)&Bs[b_k][b_n]     = bv0;
        *(float4*)&Bs[b_k + 8][b_n] = bv1;
        __syncthreads();
        #pragma unroll
        for (int k = 0; k < 16; ++k) {
            float a[8], b[8];
            *(float4*)(a)     = *(const float4*)&As[k][row * 8];
            *(float4*)(a + 4) = *(const float4*)&As[k][row * 8 + 4];
            *(float4*)(b)     = *(const float4*)&Bs[k][col * 8];
            *(float4*)(b + 4) = *(const float4*)&Bs[k][col * 8 + 4];
            #pragma unroll
            for (int i = 0; i < 8; i++)
                #pragma unroll
                for (int j = 0; j < 8; j++)
                    acc[i][j] = fmaf(a[i], b[j], acc[i][j]);
        }
        __syncthreads();
    }
    // epilogue
    #pragma unroll
    for (int i = 0; i < 8; i++) {
        int m = bm + row * 8 + i;
        float* crow = C + (size_t)m * ldc;
        #pragma unroll
        for (int j = 0; j < 8; j += 4) {
            int n0 = bn + col * 8 + j;
            float4 v = make_float4(acc[i][j], acc[i][j + 1], acc[i][j + 2], acc[i][j + 3]);
            if (bias) {
                const float4 bb = *(const float4*)&bias[n0];
                v.x += bb.x; v.y += bb.y; v.z += bb.z; v.w += bb.w;
            }
            if (resid) {
                const float4 rr = *(const float4*)(resid + (size_t)m * ldr + n0);
                v.x += rr.x; v.y += rr.y; v.z += rr.z; v.w += rr.w;
            }
            *(float4*)(crow + n0) = v;
        }
    }
}

// ---------------- SGEMM (round-1 verbatim; used for dt_proj K=24) ----------------
__global__ __launch_bounds__(256) void sgemm(
    const float* __restrict__ A, int lda,
    const float* __restrict__ Bt,
    const float* __restrict__ bias,
    const float* __restrict__ resid, int ldr,
    float* __restrict__ C, int ldc,
    int M, int N, int K, int act)
{
    __shared__ float As[8][132];
    __shared__ float Bs[8][128];
    int tid = threadIdx.x;
    int bm = blockIdx.y * 128, bn = blockIdx.x * 128;
    int row = tid / 16, col = tid % 16;

    float acc[8][8];
    #pragma unroll
    for (int i = 0; i < 8; i++)
        #pragma unroll
        for (int j = 0; j < 8; j++) acc[i][j] = 0.f;

    int a_m = tid / 2;
    int a_k = (tid % 2) * 4;
    int b_n = (tid % 32) * 4;
    int b_k = tid / 32;

    int ktiles = (K + 7) / 8;
    for (int t = 0; t < ktiles; ++t) {
        int k0 = t * 8;
        {
            float4 av = make_float4(0.f, 0.f, 0.f, 0.f);
            int gm = bm + a_m, gk = k0 + a_k;
            const float* ap = A + (size_t)gm * lda;
            if (gk + 3 < K) {
                av = *(const float4*)(ap + gk);
            } else {
                if (gk + 0 < K) av.x = ap[gk + 0];
                if (gk + 1 < K) av.y = ap[gk + 1];
                if (gk + 2 < K) av.z = ap[gk + 2];
                if (gk + 3 < K) av.w = ap[gk + 3];
            }
            As[a_k + 0][a_m] = av.x;
            As[a_k + 1][a_m] = av.y;
            As[a_k + 2][a_m] = av.z;
            As[a_k + 3][a_m] = av.w;
        }
        {
            float4 bv = make_float4(0.f, 0.f, 0.f, 0.f);
            int gn = bn + b_n, gk = k0 + b_k;
            if (gk < K) {
                const float* bp = Bt + (size_t)gk * N;
                if (gn + 3 < N) {
                    bv = *(const float4*)(bp + gn);
                } else {
                    if (gn + 0 < N) bv.x = bp[gn + 0];
                    if (gn + 1 < N) bv.y = bp[gn + 1];
                    if (gn + 2 < N) bv.z = bp[gn + 2];
                    if (gn + 3 < N) bv.w = bp[gn + 3];
                }
            }
            *(float4*)&Bs[b_k][b_n] = bv;
        }
        __syncthreads();
        #pragma unroll
        for (int k = 0; k < 8; ++k) {
            float a[8], b[8];
            *(float4*)(a)     = *(const float4*)&As[k][row * 8];
            *(float4*)(a + 4) = *(const float4*)&As[k][row * 8 + 4];
            *(float4*)(b)     = *(const float4*)&Bs[k][col * 8];
            *(float4*)(b + 4) = *(const float4*)&Bs[k][col * 8 + 4];
            #pragma unroll
            for (int i = 0; i < 8; i++)
                #pragma unroll
                for (int j = 0; j < 8; j++)
                    acc[i][j] = fmaf(a[i], b[j], acc[i][j]);
        }
        __syncthreads();
    }
    #pragma unroll
    for (int i = 0; i < 8; i++) {
        int m = bm + row * 8 + i;
        if (m >= M) continue;
        #pragma unroll
        for (int j = 0; j < 8; j++) {
            int n = bn + col * 8 + j;
            if (n >= N) continue;
            float v = acc[i][j];
            if (bias) v += bias[n];
            if (act == 1) {  // softplus
                v = (v > 20.f) ? v : log1pf(expf(v));
            }
            if (resid) v += resid[(size_t)m * ldr + n];
            C[(size_t)m * ldc + n] = v;
        }
    }
}

// ---------------- narrow SGEMM: tile 128x64, Bt padded [K][64] ----------------
__global__ __launch_bounds__(256) void sgemm64(
    const float* __restrict__ A, int lda,
    const float* __restrict__ Bt,          // [K][64]
    float* __restrict__ C, int ldc,
    int Nstore, int K)
{
    __shared__ float As[8][132];
    __shared__ float Bs[8][64];
    int tid = threadIdx.x;
    int bm = blockIdx.y * 128;
    int row = tid / 16, col = tid % 16;

    float acc[8][4];
    #pragma unroll
    for (int i = 0; i < 8; i++)
        #pragma unroll
        for (int j = 0; j < 4; j++) acc[i][j] = 0.f;

    int a_m = tid / 2;
    int a_k = (tid % 2) * 4;
    int b_k = tid >> 4;
    int b_n = (tid & 15) * 4;

    int ktiles = K / 8;
    for (int t = 0; t < ktiles; ++t) {
        int k0 = t * 8;
        {
            float4 av = *(const float4*)(A + (size_t)(bm + a_m) * lda + k0 + a_k);
            As[a_k + 0][a_m] = av.x;
            As[a_k + 1][a_m] = av.y;
            As[a_k + 2][a_m] = av.z;
            As[a_k + 3][a_m] = av.w;
        }
        if (tid < 128) {
            float4 bv = *(const float4*)(Bt + (size_t)(k0 + b_k) * 64 + b_n);
            *(float4*)&Bs[b_k][b_n] = bv;
        }
        __syncthreads();
        #pragma unroll
        for (int k = 0; k < 8; ++k) {
            float a[8], b[4];
            *(float4*)(a)     = *(const float4*)&As[k][row * 8];
            *(float4*)(a + 4) = *(const float4*)&As[k][row * 8 + 4];
            *(float4*)(b)     = *(const float4*)&Bs[k][col * 4];
            #pragma unroll
            for (int i = 0; i < 8; i++)
                #pragma unroll
                for (int j = 0; j < 4; j++)
                    acc[i][j] = fmaf(a[i], b[j], acc[i][j]);
        }
        __syncthreads();
    }
    #pragma unroll
    for (int i = 0; i < 8; i++) {
        int m = bm + row * 8 + i;
        int n0 = col * 4;
        if (n0 >= Nstore) continue;
        *(float4*)(C + (size_t)m * ldc + n0) =
            make_float4(acc[i][0], acc[i][1], acc[i][2], acc[i][3]);
    }
}

// ---------------- causal depthwise conv1d (K=4) + SiLU ----------------
__global__ void dwconv1d_silu(const float* __restrict__ x, int xstride,
                              const float* __restrict__ w,
                              const float* __restrict__ bias,
                              float* __restrict__ out) {
    int idx = blockIdx.x * blockDim.x + threadIdx.x;
    if (idx >= MROWS * DINNER) return;
    int d = idx % DINNER;
    int m = idx / DINNER;
    int l = m & (LSEQ - 1);
    float acc = bias[d];
    #pragma unroll
    for (int k = 0; k < 4; k++) {
        int ll = l - 3 + k;
        if (ll >= 0)
            acc += w[d * 4 + k] * x[(size_t)(m + (ll - l)) * xstride + d];
    }
    out[(size_t)m * DINNER + d] = silu_f(acc);
}

// ---------------- selective scan (+ fused silu(z) gate, z PREFETCHED) --------
// Two-phase step loop: phase 1 = serial h updates (short expf+fma chain),
// phase 2 = pipelined shuffle reductions + gated stores from smem z.
__global__ __launch_bounds__(256) void scan_kernel(
    const float* __restrict__ u,
    const float* __restrict__ dt,
    const float* __restrict__ dbl,
    const float* __restrict__ Cm,
    const float* __restrict__ A_log,
    const float* __restrict__ Dp,
    const float* __restrict__ xz,   // z at column offset 768, stride 1536
    float* __restrict__ y)
{
    int b  = blockIdx.x / 48;
    int d0 = (blockIdx.x % 48) * 16;
    int tid = threadIdx.x;
    int dl = tid / 16;
    int n  = tid % 16;
    int d = d0 + dl;
    float a = -expf(A_log[d * 16 + n]);
    float Dv = Dp[d];
    __shared__ float sdt[16][16], su[16][16], sB[16][17], sC[16][17], sz[16][16];
    float h = 0.f;
    size_t base = (size_t)b * LSEQ;
    int lo = tid / 16, c = tid % 16;
    for (int l0 = 0; l0 < LSEQ; l0 += 16) {
        size_t m = base + l0 + lo;
        sdt[lo][c] = dt[m * 768 + d0 + c];
        su [lo][c] = u [m * 768 + d0 + c];
        sB [lo][c] = dbl[m * 40 + 24 + c];
        sC [lo][c] = Cm [m * 16 + c];
        sz [lo][c] = xz[m * 1536 + 768 + d0 + c];
        __syncthreads();
        // phase 1: serial recurrence, buffer partial products
        float p[16];
        #pragma unroll
        for (int s = 0; s < 16; ++s) {
            float dtv = sdt[s][dl];
            float uv  = su [s][dl];
            h = expf(dtv * a) * h + dtv * uv * sB[s][n];
            p[s] = h * sC[s][n];
        }
        // phase 2: pipelined reductions + stores
        #pragma unroll
        for (int s = 0; s < 16; ++s) {
            float q = p[s];
            q += __shfl_xor_sync(0xffffffffu, q, 8);
            q += __shfl_xor_sync(0xffffffffu, q, 4);
            q += __shfl_xor_sync(0xffffffffu, q, 2);
            q += __shfl_xor_sync(0xffffffffu, q, 1);
            if (n == 0) {
                size_t mm = base + l0 + s;
                y[mm * 768 + d] = (q + su[s][dl] * Dv) * silu_f(sz[s][dl]);
            }
        }
        __syncthreads();
    }
}

// ---------------- (B,L,C) -> (B,C,L) transpose ----------------
__global__ void transpose_LC(const float* __restrict__ in, float* __restrict__ out) {
    __shared__ float t[32][33];
    int bb = blockIdx.z;
    int c0 = blockIdx.x * 32, l0 = blockIdx.y * 32;
    const float* ip = in + (size_t)bb * LSEQ * DIMC;
    float* op = out + (size_t)bb * DIMC * LSEQ;
    int tx = threadIdx.x, ty = threadIdx.y;
    #pragma unroll
    for (int i = 0; i < 32; i += 8)
        t[ty + i][tx] = ip[(size_t)(l0 + ty + i) * DIMC + c0 + tx];
    __syncthreads();
    #pragma unroll
    for (int i = 0; i < 32; i += 8)
        op[(size_t)(c0 + ty + i) * LSEQ + l0 + tx] = t[tx][ty + i];
}

// ---------------- final 3x3 depthwise conv (SAME) on (B,C,64,64) ----------------
__global__ void dwconv3x3(const float* __restrict__ img, const float* __restrict__ w,
                          const float* __restrict__ bias, float* __restrict__ out) {
    int idx = blockIdx.x * blockDim.x + threadIdx.x;
    if (idx >= BSZ * DIMC * 64 * 64) return;
    int wv = idx & 63;
    int h  = (idx >> 6) & 63;
    int c  = (idx >> 12) % DIMC;
    int b  = idx / (DIMC * 4096);
    const float* ip = img + ((size_t)b * DIMC + c) * 4096;
    const float* wc = w + c * 9;
    float acc = bias[c];
    #pragma unroll
    for (int dh = -1; dh <= 1; dh++) {
        int hh = h + dh;
        if (hh < 0 || hh >= 64) continue;
        #pragma unroll
        for (int dw = -1; dw <= 1; dw++) {
            int ww = wv + dw;
            if (ww < 0 || ww >= 64) continue;
            acc += wc[(dh + 1) * 3 + (dw + 1)] * ip[hh * 64 + ww];
        }
    }
    out[idx] = acc;
}

// ---------------- host ----------------
static void g16(const float* A, int lda, const float* Bt,
                const float* bias, const float* resid, int ldr,
                float* C, int ldc, int N, int K) {
    dim3 grid(N / 128, MROWS / 128);
    sgemm16<false><<<grid, 256>>>(A, lda, nullptr, 0, 0, Bt, bias, resid, ldr,
                                  C, ldc, N, K);
}

extern "C" void kernel_launch(void* const* d_in, const int* in_sizes, int n_in,
                              void* d_out, int out_size) {
    const float* ms          = (const float*)d_in[0];
    const float* pan         = (const float*)d_in[1];
    const float* reduce_W    = (const float*)d_in[2];
    const float* reduce_b    = (const float*)d_in[3];
    const float* ln1_w       = (const float*)d_in[4];
    const float* ln1_b       = (const float*)d_in[5];
    const float* ln2_w       = (const float*)d_in[6];
    const float* ln2_b       = (const float*)d_in[7];
    const float* ln3_w       = (const float*)d_in[8];
    const float* ln3_b       = (const float*)d_in[9];
    const float* in_proj_W   = (const float*)d_in[10];
    const float* in_proj_b_W = (const float*)d_in[11];
    const float* in_proj_c_W = (const float*)d_in[12];
    const float* conv_w      = (const float*)d_in[13];
    const float* conv_bias   = (const float*)d_in[14];
    const float* conv_b_w    = (const float*)d_in[15];
    const float* conv_b_bias = (const float*)d_in[16];
    const float* conv_c_w    = (const float*)d_in[17];
    const float* conv_c_bias = (const float*)d_in[18];
    const float* x_proj_W    = (const float*)d_in[19];
    const float* x_proj_c_W  = (const float*)d_in[20];
    const float* dt_proj_W   = (const float*)d_in[21];
    const float* dt_proj_bias= (const float*)d_in[22];
    const float* A_log       = (const float*)d_in[23];
    const float* Dvec        = (const float*)d_in[24];
    const float* out_proj_W  = (const float*)d_in[25];
    const float* dwconv_w    = (const float*)d_in[26];
    const float* dwconv_b    = (const float*)d_in[27];
    float* out = (float*)d_out;

    float *pWr, *pWin, *pWinb, *pWinc, *pWout, *pWxp64, *pWxpc64, *pWdt;
    float *pmsn, *ppann, *pred, *pconn, *pxz, *pxbp, *pxcp;
    float *px, *pxb, *pxc, *pdbl, *pdt, *pcm, *py, *pgf, *pimg;
    cudaGetSymbolAddress((void**)&pWr,     g_Wr_t);
    cudaGetSymbolAddress((void**)&pWin,    g_Win_t);
    cudaGetSymbolAddress((void**)&pWinb,   g_Winb_t);
    cudaGetSymbolAddress((void**)&pWinc,   g_Winc_t);
    cudaGetSymbolAddress((void**)&pWout,   g_Wout_t);
    cudaGetSymbolAddress((void**)&pWxp64,  g_Wxp64);
    cudaGetSymbolAddress((void**)&pWxpc64, g_Wxpc64);
    cudaGetSymbolAddress((void**)&pWdt,    g_Wdt_t);
    cudaGetSymbolAddress((void**)&pmsn,    g_msn);
    cudaGetSymbolAddress((void**)&ppann,   g_pann);
    cudaGetSymbolAddress((void**)&pred,    g_red);
    cudaGetSymbolAddress((void**)&pconn,   g_conn);
    cudaGetSymbolAddress((void**)&pxz,     g_xz);
    cudaGetSymbolAddress((void**)&pxbp,    g_xbp);
    cudaGetSymbolAddress((void**)&pxcp,    g_xcp);
    cudaGetSymbolAddress((void**)&px,      g_x);
    cudaGetSymbolAddress((void**)&pxb,     g_xb);
    cudaGetSymbolAddress((void**)&pxc,     g_xc);
    cudaGetSymbolAddress((void**)&pdbl,    g_dbl);
    cudaGetSymbolAddress((void**)&pdt,     g_dt);
    cudaGetSymbolAddress((void**)&pcm,     g_cm);
    cudaGetSymbolAddress((void**)&py,      g_y);
    cudaGetSymbolAddress((void**)&pgf,     g_gf);
    cudaGetSymbolAddress((void**)&pimg,    g_img);

    auto wt = [](const float* in, float* o, int N, int K) {
        int tot = N * K;
        wt_transpose<<<(tot + 255) / 256, 256>>>(in, o, N, K);
    };

    // launches 1-5
    wt(reduce_W,  pWr,  384, 768);                          // 1
    wt(in_proj_W, pWin, 1536, 384);                         // 2
    ln_kernel<<<MROWS, 128>>>(ms,  ln1_w, ln1_b, pmsn);     // 3
    ln_kernel<<<MROWS, 128>>>(pan, ln2_w, ln2_b, ppann);    // 4
    wt(in_proj_b_W, pWinb, 768, 384);                       // 5

    // 6: reduce GEMM with fused concat (A = [ms | pan])
    {
        dim3 grid(384 / 128, MROWS / 128);
        sgemm16<true><<<grid, 256>>>(ms, 384, pan, 384, 384, pWr,
                                     reduce_b, nullptr, 0, pred, 384, 384, 768);
    }

    // in_proj GEMM
    g16(pmsn, 384, pWin, nullptr, nullptr, 0, pxz, 1536, 1536, 384);

    ln_kernel<<<MROWS, 128>>>(pred, ln3_w, ln3_b, pconn);

    wt(in_proj_c_W, pWinc, 768, 384);
    wt(dt_proj_W,   pWdt,  768, 24);
    wt(out_proj_W,  pWout, 384, 768);
    wt_transpose_pad64<<<(768 * 64 + 255) / 256, 256>>>(x_proj_W,   pWxp64,  40, 768);
    wt_transpose_pad64<<<(768 * 64 + 255) / 256, 256>>>(x_proj_c_W, pWxpc64, 16, 768);

    g16(ppann, 384, pWinb, nullptr, nullptr, 0, pxbp, 768, 768, 384);
    g16(pconn, 384, pWinc, nullptr, nullptr, 0, pxcp, 768, 768, 384);

    // depthwise causal convs + SiLU
    {
        int tot = MROWS * DINNER;
        int blocks = (tot + 255) / 256;
        dwconv1d_silu<<<blocks, 256>>>(pxz,  1536, conv_w,   conv_bias,   px);
        dwconv1d_silu<<<blocks, 256>>>(pxbp, 768,  conv_b_w, conv_b_bias, pxb);
        dwconv1d_silu<<<blocks, 256>>>(pxcp, 768,  conv_c_w, conv_c_bias, pxc);
    }

    // narrow projections (BN=64 kernel, padded transposed weights)
    sgemm64<<<dim3(1, MROWS / 128), 256>>>(pxb, 768, pWxp64,  pdbl, 40, 40, 768);
    sgemm64<<<dim3(1, MROWS / 128), 256>>>(pxc, 768, pWxpc64, pcm,  16, 16, 768);

    // dt_proj (fp32, K=24, softplus + bias) — round-1 bounds-checked kernel
    {
        dim3 grid(6, MROWS / 128);
        sgemm<<<grid, 256>>>(pdbl, 40, pWdt, dt_proj_bias, nullptr, 0,
                             pdt, 768, MROWS, 768, 24, 1);
    }

    // selective scan with fused silu(z) gate (z prefetched to smem)
    scan_kernel<<<BSZ * 48, 256>>>(px, pdt, pdbl, pcm, A_log, Dvec, pxz, py);

    // out_proj + residual(ms)
    g16(py, 768, pWout, nullptr, ms, 384, pgf, 384, 384, 768);

    // (B,L,C) -> (B,C,HW) transpose, then 3x3 depthwise conv
    {
        dim3 grid(DIMC / 32, LSEQ / 32, BSZ);
        dim3 blk(32, 8);
        transpose_LC<<<grid, blk>>>(pgf, pimg);
    }
    {
        int tot = BSZ * DIMC * 64 * 64;
        dwconv3x3<<<(tot + 255) / 256, 256>>>(pimg, dwconv_w, dwconv_b, out);
    }
}

// round 16
// speedup vs baseline: 2.2603x; 1.0162x over previous
#include <cuda_runtime.h>
#include <math.h>
#include <stdint.h>

#define MROWS  16384
#define LSEQ   4096
#define BSZ    4
#define DIMC   384
#define DINNER 768
#define DSTATE 16
#define DTRANK 24

// ---------------- scratch (device globals; allocation-free) ----------------
__device__ float g_Wr_t  [768*384];    // reduce_W^T   (K=768, N=384)
__device__ float g_Win_t [384*1536];   // in_proj_W^T
__device__ float g_Winb_t[384*768];
__device__ float g_Winc_t[384*768];
__device__ float g_Wout_t[768*384];
__device__ float g_Wxp64 [768*64];     // x_proj_W^T padded  [768][64]
__device__ float g_Wxpc64[768*64];     // x_proj_c_W^T padded [768][64]
__device__ float g_Wdt_t [24*768];

__device__ float g_msn   [MROWS*384];
__device__ float g_pann  [MROWS*384];
__device__ float g_red   [MROWS*384];
__device__ float g_conn  [MROWS*384];
__device__ float g_xz    [(size_t)MROWS*1536];
__device__ float g_xbp   [MROWS*768];
__device__ float g_xcp   [MROWS*768];
__device__ float g_x     [MROWS*768];
__device__ float g_xb    [MROWS*768];
__device__ float g_xc    [MROWS*768];
__device__ float g_dbl   [MROWS*40];
__device__ float g_dt    [MROWS*768];
__device__ float g_cm    [MROWS*16];
__device__ float g_y     [MROWS*768];
__device__ float g_gf    [MROWS*384];
__device__ float g_img   [MROWS*384];

// ---------------- helpers ----------------
__device__ __forceinline__ float silu_f(float v) {
    return v / (1.f + __expf(-v));
}

// ---------------- weight transpose: out[k*N+n] = in[n*K+k] ----------------
__global__ void wt_transpose(const float* __restrict__ in, float* __restrict__ out,
                             int N, int K) {
    int idx = blockIdx.x * blockDim.x + threadIdx.x;
    if (idx >= N * K) return;
    int n = idx % N;
    int k = idx / N;
    out[(size_t)k * N + n] = in[(size_t)n * K + k];
}

// ---------------- transpose + pad: in [Nin,K] -> out [K,64] (pad cols zero) ----
__global__ void wt_transpose_pad64(const float* __restrict__ in, float* __restrict__ out,
                                   int Nin, int K) {
    int idx = blockIdx.x * blockDim.x + threadIdx.x;
    if (idx >= K * 64) return;
    int n = idx % 64;
    int k = idx / 64;
    out[idx] = (n < Nin) ? in[(size_t)n * K + k] : 0.f;
}

// ---------------- layernorm over 384, one block (128 thr) per row ----------------
__global__ __launch_bounds__(128) void ln_kernel(const float* __restrict__ x,
                                                 const float* __restrict__ w,
                                                 const float* __restrict__ b,
                                                 float* __restrict__ out) {
    int m = blockIdx.x;
    int t = threadIdx.x;
    const float* row = x + (size_t)m * 384;
    float v0 = row[t], v1 = row[t + 128], v2 = row[t + 256];
    float s = v0 + v1 + v2;
    __shared__ float red1[4], red2[4];
    #pragma unroll
    for (int o = 16; o; o >>= 1) s += __shfl_xor_sync(0xffffffffu, s, o);
    if ((t & 31) == 0) red1[t >> 5] = s;
    __syncthreads();
    float mu = (red1[0] + red1[1] + red1[2] + red1[3]) * (1.f / 384.f);
    float d0 = v0 - mu, d1 = v1 - mu, d2 = v2 - mu;
    float q = d0 * d0 + d1 * d1 + d2 * d2;
    #pragma unroll
    for (int o = 16; o; o >>= 1) q += __shfl_xor_sync(0xffffffffu, q, o);
    if ((t & 31) == 0) red2[t >> 5] = q;
    __syncthreads();
    float var = (red2[0] + red2[1] + red2[2] + red2[3]) * (1.f / 384.f);
    float inv = rsqrtf(var + 1e-5f);
    float* o = out + (size_t)m * 384;
    o[t]       = d0 * inv * w[t]       + b[t];
    o[t + 128] = d1 * inv * w[t + 128] + b[t + 128];
    o[t + 256] = d2 * inv * w[t + 256] + b[t + 256];
}

// ---------------- SGEMM BK=16, no bounds checks (big GEMMs) ----------------
// C[M,N] = A[M,K] * Bt[K,N] (+bias,+resid). M,N mult of 128, K mult of 16.
// SPLIT: A columns k >= ksplit come from A2 (concat fusion); dead code when false.
template<bool SPLIT>
__global__ __launch_bounds__(256, 2) void sgemm16(
    const float* __restrict__ A, int lda,
    const float* __restrict__ A2, int lda2, int ksplit,
    const float* __restrict__ Bt,
    const float* __restrict__ bias,
    const float* __restrict__ resid, int ldr,
    float* __restrict__ C, int ldc,
    int N, int K)
{
    __shared__ float As[16][132];
    __shared__ float Bs[16][128];
    int tid = threadIdx.x;
    int bm = blockIdx.y * 128, bn = blockIdx.x * 128;
    int row = tid / 16, col = tid % 16;

    float acc[8][8];
    #pragma unroll
    for (int i = 0; i < 8; i++)
        #pragma unroll
        for (int j = 0; j < 8; j++) acc[i][j] = 0.f;

    int a_m = tid >> 1;
    int a_k = (tid & 1) * 8;
    int b_n = (tid & 31) * 4;
    int b_k = tid >> 5;

    const float* ap  = A + (size_t)(bm + a_m) * lda;
    const float* ap2 = SPLIT ? (A2 + (size_t)(bm + a_m) * lda2) : nullptr;
    const float* bp0 = Bt + (size_t)b_k * N + bn + b_n;

    int ktiles = K >> 4;
    for (int t = 0; t < ktiles; ++t) {
        int k0 = t * 16;
        float4 a0, a1;
        if (SPLIT) {
            int gk = k0 + a_k;
            const float* src = (gk >= ksplit) ? (ap2 + (gk - ksplit)) : (ap + gk);
            a0 = *(const float4*)src;
            a1 = *(const float4*)(src + 4);
        } else {
            a0 = *(const float4*)(ap + k0 + a_k);
            a1 = *(const float4*)(ap + k0 + a_k + 4);
        }
        float4 bv0 = *(const float4*)(bp0 + (size_t)k0 * N);
        float4 bv1 = *(const float4*)(bp0 + (size_t)(k0 + 8) * N);
        As[a_k + 0][a_m] = a0.x;
        As[a_k + 1][a_m] = a0.y;
        As[a_k + 2][a_m] = a0.z;
        As[a_k + 3][a_m] = a0.w;
        As[a_k + 4][a_m] = a1.x;
        As[a_k + 5][a_m] = a1.y;
        As[a_k + 6][a_m] = a1.z;
        As[a_k + 7][a_m] = a1.w;
        *(float4*)&Bs[b_k][b_n]     = bv0;
        *(float4*)&Bs[b_k + 8][b_n] = bv1;
        __syncthreads();
        #pragma unroll
        for (int k = 0; k < 16; ++k) {
            float a[8], b[8];
            *(float4*)(a)     = *(const float4*)&As[k][row * 8];
            *(float4*)(a + 4) = *(const float4*)&As[k][row * 8 + 4];
            *(float4*)(b)     = *(const float4*)&Bs[k][col * 8];
            *(float4*)(b + 4) = *(const float4*)&Bs[k][col * 8 + 4];
            #pragma unroll
            for (int i = 0; i < 8; i++)
                #pragma unroll
                for (int j = 0; j < 8; j++)
                    acc[i][j] = fmaf(a[i], b[j], acc[i][j]);
        }
        __syncthreads();
    }
    // epilogue
    #pragma unroll
    for (int i = 0; i < 8; i++) {
        int m = bm + row * 8 + i;
        float* crow = C + (size_t)m * ldc;
        #pragma unroll
        for (int j = 0; j < 8; j += 4) {
            int n0 = bn + col * 8 + j;
            float4 v = make_float4(acc[i][j], acc[i][j + 1], acc[i][j + 2], acc[i][j + 3]);
            if (bias) {
                const float4 bb = *(const float4*)&bias[n0];
                v.x += bb.x; v.y += bb.y; v.z += bb.z; v.w += bb.w;
            }
            if (resid) {
                const float4 rr = *(const float4*)(resid + (size_t)m * ldr + n0);
                v.x += rr.x; v.y += rr.y; v.z += rr.z; v.w += rr.w;
            }
            *(float4*)(crow + n0) = v;
        }
    }
}

// ---------------- SGEMM (round-1 verbatim; used for dt_proj K=24) ----------------
__global__ __launch_bounds__(256) void sgemm(
    const float* __restrict__ A, int lda,
    const float* __restrict__ Bt,
    const float* __restrict__ bias,
    const float* __restrict__ resid, int ldr,
    float* __restrict__ C, int ldc,
    int M, int N, int K, int act)
{
    __shared__ float As[8][132];
    __shared__ float Bs[8][128];
    int tid = threadIdx.x;
    int bm = blockIdx.y * 128, bn = blockIdx.x * 128;
    int row = tid / 16, col = tid % 16;

    float acc[8][8];
    #pragma unroll
    for (int i = 0; i < 8; i++)
        #pragma unroll
        for (int j = 0; j < 8; j++) acc[i][j] = 0.f;

    int a_m = tid / 2;
    int a_k = (tid % 2) * 4;
    int b_n = (tid % 32) * 4;
    int b_k = tid / 32;

    int ktiles = (K + 7) / 8;
    for (int t = 0; t < ktiles; ++t) {
        int k0 = t * 8;
        {
            float4 av = make_float4(0.f, 0.f, 0.f, 0.f);
            int gm = bm + a_m, gk = k0 + a_k;
            const float* ap = A + (size_t)gm * lda;
            if (gk + 3 < K) {
                av = *(const float4*)(ap + gk);
            } else {
                if (gk + 0 < K) av.x = ap[gk + 0];
                if (gk + 1 < K) av.y = ap[gk + 1];
                if (gk + 2 < K) av.z = ap[gk + 2];
                if (gk + 3 < K) av.w = ap[gk + 3];
            }
            As[a_k + 0][a_m] = av.x;
            As[a_k + 1][a_m] = av.y;
            As[a_k + 2][a_m] = av.z;
            As[a_k + 3][a_m] = av.w;
        }
        {
            float4 bv = make_float4(0.f, 0.f, 0.f, 0.f);
            int gn = bn + b_n, gk = k0 + b_k;
            if (gk < K) {
                const float* bp = Bt + (size_t)gk * N;
                if (gn + 3 < N) {
                    bv = *(const float4*)(bp + gn);
                } else {
                    if (gn + 0 < N) bv.x = bp[gn + 0];
                    if (gn + 1 < N) bv.y = bp[gn + 1];
                    if (gn + 2 < N) bv.z = bp[gn + 2];
                    if (gn + 3 < N) bv.w = bp[gn + 3];
                }
            }
            *(float4*)&Bs[b_k][b_n] = bv;
        }
        __syncthreads();
        #pragma unroll
        for (int k = 0; k < 8; ++k) {
            float a[8], b[8];
            *(float4*)(a)     = *(const float4*)&As[k][row * 8];
            *(float4*)(a + 4) = *(const float4*)&As[k][row * 8 + 4];
            *(float4*)(b)     = *(const float4*)&Bs[k][col * 8];
            *(float4*)(b + 4) = *(const float4*)&Bs[k][col * 8 + 4];
            #pragma unroll
            for (int i = 0; i < 8; i++)
                #pragma unroll
                for (int j = 0; j < 8; j++)
                    acc[i][j] = fmaf(a[i], b[j], acc[i][j]);
        }
        __syncthreads();
    }
    #pragma unroll
    for (int i = 0; i < 8; i++) {
        int m = bm + row * 8 + i;
        if (m >= M) continue;
        #pragma unroll
        for (int j = 0; j < 8; j++) {
            int n = bn + col * 8 + j;
            if (n >= N) continue;
            float v = acc[i][j];
            if (bias) v += bias[n];
            if (act == 1) {  // softplus
                v = (v > 20.f) ? v : log1pf(expf(v));
            }
            if (resid) v += resid[(size_t)m * ldr + n];
            C[(size_t)m * ldc + n] = v;
        }
    }
}

// ---------------- narrow SGEMM: tile 128x64, Bt padded [K][64] ----------------
__global__ __launch_bounds__(256) void sgemm64(
    const float* __restrict__ A, int lda,
    const float* __restrict__ Bt,          // [K][64]
    float* __restrict__ C, int ldc,
    int Nstore, int K)
{
    __shared__ float As[8][132];
    __shared__ float Bs[8][64];
    int tid = threadIdx.x;
    int bm = blockIdx.y * 128;
    int row = tid / 16, col = tid % 16;

    float acc[8][4];
    #pragma unroll
    for (int i = 0; i < 8; i++)
        #pragma unroll
        for (int j = 0; j < 4; j++) acc[i][j] = 0.f;

    int a_m = tid / 2;
    int a_k = (tid % 2) * 4;
    int b_k = tid >> 4;
    int b_n = (tid & 15) * 4;

    int ktiles = K / 8;
    for (int t = 0; t < ktiles; ++t) {
        int k0 = t * 8;
        {
            float4 av = *(const float4*)(A + (size_t)(bm + a_m) * lda + k0 + a_k);
            As[a_k + 0][a_m] = av.x;
            As[a_k + 1][a_m] = av.y;
            As[a_k + 2][a_m] = av.z;
            As[a_k + 3][a_m] = av.w;
        }
        if (tid < 128) {
            float4 bv = *(const float4*)(Bt + (size_t)(k0 + b_k) * 64 + b_n);
            *(float4*)&Bs[b_k][b_n] = bv;
        }
        __syncthreads();
        #pragma unroll
        for (int k = 0; k < 8; ++k) {
            float a[8], b[4];
            *(float4*)(a)     = *(const float4*)&As[k][row * 8];
            *(float4*)(a + 4) = *(const float4*)&As[k][row * 8 + 4];
            *(float4*)(b)     = *(const float4*)&Bs[k][col * 4];
            #pragma unroll
            for (int i = 0; i < 8; i++)
                #pragma unroll
                for (int j = 0; j < 4; j++)
                    acc[i][j] = fmaf(a[i], b[j], acc[i][j]);
        }
        __syncthreads();
    }
    #pragma unroll
    for (int i = 0; i < 8; i++) {
        int m = bm + row * 8 + i;
        int n0 = col * 4;
        if (n0 >= Nstore) continue;
        *(float4*)(C + (size_t)m * ldc + n0) =
            make_float4(acc[i][0], acc[i][1], acc[i][2], acc[i][3]);
    }
}

// ---------------- causal depthwise conv1d (K=4) + SiLU ----------------
__global__ void dwconv1d_silu(const float* __restrict__ x, int xstride,
                              const float* __restrict__ w,
                              const float* __restrict__ bias,
                              float* __restrict__ out) {
    int idx = blockIdx.x * blockDim.x + threadIdx.x;
    if (idx >= MROWS * DINNER) return;
    int d = idx % DINNER;
    int m = idx / DINNER;
    int l = m & (LSEQ - 1);
    float acc = bias[d];
    #pragma unroll
    for (int k = 0; k < 4; k++) {
        int ll = l - 3 + k;
        if (ll >= 0)
            acc += w[d * 4 + k] * x[(size_t)(m + (ll - l)) * xstride + d];
    }
    out[(size_t)m * DINNER + d] = silu_f(acc);
}

// ---------------- selective scan (+ fused silu(z) gate, z prefetched) --------
// Phase 0: precompute decay e[s] and drive g[s] (independent of h, pipelined).
// Phase 1: bare 16-FFMA recurrence chain.  Phase 2: pipelined reductions+stores.
__global__ __launch_bounds__(256) void scan_kernel(
    const float* __restrict__ u,
    const float* __restrict__ dt,
    const float* __restrict__ dbl,
    const float* __restrict__ Cm,
    const float* __restrict__ A_log,
    const float* __restrict__ Dp,
    const float* __restrict__ xz,   // z at column offset 768, stride 1536
    float* __restrict__ y)
{
    int b  = blockIdx.x / 48;
    int d0 = (blockIdx.x % 48) * 16;
    int tid = threadIdx.x;
    int dl = tid / 16;
    int n  = tid % 16;
    int d = d0 + dl;
    float a = -expf(A_log[d * 16 + n]);
    float Dv = Dp[d];
    __shared__ float sdt[16][16], su[16][16], sB[16][17], sC[16][17], sz[16][16];
    float h = 0.f;
    size_t base = (size_t)b * LSEQ;
    int lo = tid / 16, c = tid % 16;
    for (int l0 = 0; l0 < LSEQ; l0 += 16) {
        size_t m = base + l0 + lo;
        sdt[lo][c] = dt[m * 768 + d0 + c];
        su [lo][c] = u [m * 768 + d0 + c];
        sB [lo][c] = dbl[m * 40 + 24 + c];
        sC [lo][c] = Cm [m * 16 + c];
        sz [lo][c] = xz[m * 1536 + 768 + d0 + c];
        __syncthreads();
        // phase 0: h-independent precompute (fully pipelined)
        float e[16], g[16];
        #pragma unroll
        for (int s = 0; s < 16; ++s) {
            float dtv = sdt[s][dl];
            e[s] = __expf(dtv * a);
            g[s] = dtv * su[s][dl] * sB[s][n];
        }
        // phase 1: bare recurrence chain + partial products
        float p[16];
        #pragma unroll
        for (int s = 0; s < 16; ++s) {
            h = fmaf(e[s], h, g[s]);
            p[s] = h * sC[s][n];
        }
        // phase 2: pipelined reductions + gated stores
        #pragma unroll
        for (int s = 0; s < 16; ++s) {
            float q = p[s];
            q += __shfl_xor_sync(0xffffffffu, q, 8);
            q += __shfl_xor_sync(0xffffffffu, q, 4);
            q += __shfl_xor_sync(0xffffffffu, q, 2);
            q += __shfl_xor_sync(0xffffffffu, q, 1);
            if (n == 0) {
                size_t mm = base + l0 + s;
                y[mm * 768 + d] = (q + su[s][dl] * Dv) * silu_f(sz[s][dl]);
            }
        }
        __syncthreads();
    }
}

// ---------------- (B,L,C) -> (B,C,L) transpose ----------------
__global__ void transpose_LC(const float* __restrict__ in, float* __restrict__ out) {
    __shared__ float t[32][33];
    int bb = blockIdx.z;
    int c0 = blockIdx.x * 32, l0 = blockIdx.y * 32;
    const float* ip = in + (size_t)bb * LSEQ * DIMC;
    float* op = out + (size_t)bb * DIMC * LSEQ;
    int tx = threadIdx.x, ty = threadIdx.y;
    #pragma unroll
    for (int i = 0; i < 32; i += 8)
        t[ty + i][tx] = ip[(size_t)(l0 + ty + i) * DIMC + c0 + tx];
    __syncthreads();
    #pragma unroll
    for (int i = 0; i < 32; i += 8)
        op[(size_t)(c0 + ty + i) * LSEQ + l0 + tx] = t[tx][ty + i];
}

// ---------------- final 3x3 depthwise conv (SAME) on (B,C,64,64) ----------------
__global__ void dwconv3x3(const float* __restrict__ img, const float* __restrict__ w,
                          const float* __restrict__ bias, float* __restrict__ out) {
    int idx = blockIdx.x * blockDim.x + threadIdx.x;
    if (idx >= BSZ * DIMC * 64 * 64) return;
    int wv = idx & 63;
    int h  = (idx >> 6) & 63;
    int c  = (idx >> 12) % DIMC;
    int b  = idx / (DIMC * 4096);
    const float* ip = img + ((size_t)b * DIMC + c) * 4096;
    const float* wc = w + c * 9;
    float acc = bias[c];
    #pragma unroll
    for (int dh = -1; dh <= 1; dh++) {
        int hh = h + dh;
        if (hh < 0 || hh >= 64) continue;
        #pragma unroll
        for (int dw = -1; dw <= 1; dw++) {
            int ww = wv + dw;
            if (ww < 0 || ww >= 64) continue;
            acc += wc[(dh + 1) * 3 + (dw + 1)] * ip[hh * 64 + ww];
        }
    }
    out[idx] = acc;
}

// ---------------- host ----------------
static void g16(const float* A, int lda, const float* Bt,
                const float* bias, const float* resid, int ldr,
                float* C, int ldc, int N, int K) {
    dim3 grid(N / 128, MROWS / 128);
    sgemm16<false><<<grid, 256>>>(A, lda, nullptr, 0, 0, Bt, bias, resid, ldr,
                                  C, ldc, N, K);
}

extern "C" void kernel_launch(void* const* d_in, const int* in_sizes, int n_in,
                              void* d_out, int out_size) {
    const float* ms          = (const float*)d_in[0];
    const float* pan         = (const float*)d_in[1];
    const float* reduce_W    = (const float*)d_in[2];
    const float* reduce_b    = (const float*)d_in[3];
    const float* ln1_w       = (const float*)d_in[4];
    const float* ln1_b       = (const float*)d_in[5];
    const float* ln2_w       = (const float*)d_in[6];
    const float* ln2_b       = (const float*)d_in[7];
    const float* ln3_w       = (const float*)d_in[8];
    const float* ln3_b       = (const float*)d_in[9];
    const float* in_proj_W   = (const float*)d_in[10];
    const float* in_proj_b_W = (const float*)d_in[11];
    const float* in_proj_c_W = (const float*)d_in[12];
    const float* conv_w      = (const float*)d_in[13];
    const float* conv_bias   = (const float*)d_in[14];
    const float* conv_b_w    = (const float*)d_in[15];
    const float* conv_b_bias = (const float*)d_in[16];
    const float* conv_c_w    = (const float*)d_in[17];
    const float* conv_c_bias = (const float*)d_in[18];
    const float* x_proj_W    = (const float*)d_in[19];
    const float* x_proj_c_W  = (const float*)d_in[20];
    const float* dt_proj_W   = (const float*)d_in[21];
    const float* dt_proj_bias= (const float*)d_in[22];
    const float* A_log       = (const float*)d_in[23];
    const float* Dvec        = (const float*)d_in[24];
    const float* out_proj_W  = (const float*)d_in[25];
    const float* dwconv_w    = (const float*)d_in[26];
    const float* dwconv_b    = (const float*)d_in[27];
    float* out = (float*)d_out;

    float *pWr, *pWin, *pWinb, *pWinc, *pWout, *pWxp64, *pWxpc64, *pWdt;
    float *pmsn, *ppann, *pred, *pconn, *pxz, *pxbp, *pxcp;
    float *px, *pxb, *pxc, *pdbl, *pdt, *pcm, *py, *pgf, *pimg;
    cudaGetSymbolAddress((void**)&pWr,     g_Wr_t);
    cudaGetSymbolAddress((void**)&pWin,    g_Win_t);
    cudaGetSymbolAddress((void**)&pWinb,   g_Winb_t);
    cudaGetSymbolAddress((void**)&pWinc,   g_Winc_t);
    cudaGetSymbolAddress((void**)&pWout,   g_Wout_t);
    cudaGetSymbolAddress((void**)&pWxp64,  g_Wxp64);
    cudaGetSymbolAddress((void**)&pWxpc64, g_Wxpc64);
    cudaGetSymbolAddress((void**)&pWdt,    g_Wdt_t);
    cudaGetSymbolAddress((void**)&pmsn,    g_msn);
    cudaGetSymbolAddress((void**)&ppann,   g_pann);
    cudaGetSymbolAddress((void**)&pred,    g_red);
    cudaGetSymbolAddress((void**)&pconn,   g_conn);
    cudaGetSymbolAddress((void**)&pxz,     g_xz);
    cudaGetSymbolAddress((void**)&pxbp,    g_xbp);
    cudaGetSymbolAddress((void**)&pxcp,    g_xcp);
    cudaGetSymbolAddress((void**)&px,      g_x);
    cudaGetSymbolAddress((void**)&pxb,     g_xb);
    cudaGetSymbolAddress((void**)&pxc,     g_xc);
    cudaGetSymbolAddress((void**)&pdbl,    g_dbl);
    cudaGetSymbolAddress((void**)&pdt,     g_dt);
    cudaGetSymbolAddress((void**)&pcm,     g_cm);
    cudaGetSymbolAddress((void**)&py,      g_y);
    cudaGetSymbolAddress((void**)&pgf,     g_gf);
    cudaGetSymbolAddress((void**)&pimg,    g_img);

    auto wt = [](const float* in, float* o, int N, int K) {
        int tot = N * K;
        wt_transpose<<<(tot + 255) / 256, 256>>>(in, o, N, K);
    };

    // launches 1-5
    wt(reduce_W,  pWr,  384, 768);                          // 1
    wt(in_proj_W, pWin, 1536, 384);                         // 2
    ln_kernel<<<MROWS, 128>>>(ms,  ln1_w, ln1_b, pmsn);     // 3
    ln_kernel<<<MROWS, 128>>>(pan, ln2_w, ln2_b, ppann);    // 4
    wt(in_proj_b_W, pWinb, 768, 384);                       // 5

    // 6: reduce GEMM with fused concat (A = [ms | pan])
    {
        dim3 grid(384 / 128, MROWS / 128);
        sgemm16<true><<<grid, 256>>>(ms, 384, pan, 384, 384, pWr,
                                     reduce_b, nullptr, 0, pred, 384, 384, 768);
    }

    // in_proj GEMM
    g16(pmsn, 384, pWin, nullptr, nullptr, 0, pxz, 1536, 1536, 384);

    ln_kernel<<<MROWS, 128>>>(pred, ln3_w, ln3_b, pconn);

    wt(in_proj_c_W, pWinc, 768, 384);
    wt(dt_proj_W,   pWdt,  768, 24);
    wt(out_proj_W,  pWout, 384, 768);
    wt_transpose_pad64<<<(768 * 64 + 255) / 256, 256>>>(x_proj_W,   pWxp64,  40, 768);
    wt_transpose_pad64<<<(768 * 64 + 255) / 256, 256>>>(x_proj_c_W, pWxpc64, 16, 768);

    g16(ppann, 384, pWinb, nullptr, nullptr, 0, pxbp, 768, 768, 384);
    g16(pconn, 384, pWinc, nullptr, nullptr, 0, pxcp, 768, 768, 384);

    // depthwise causal convs + SiLU
    {
        int tot = MROWS * DINNER;
        int blocks = (tot + 255) / 256;
        dwconv1d_silu<<<blocks, 256>>>(pxz,  1536, conv_w,   conv_bias,   px);
        dwconv1d_silu<<<blocks, 256>>>(pxbp, 768,  conv_b_w, conv_b_bias, pxb);
        dwconv1d_silu<<<blocks, 256>>>(pxcp, 768,  conv_c_w, conv_c_bias, pxc);
    }

    // narrow projections (BN=64 kernel, padded transposed weights)
    sgemm64<<<dim3(1, MROWS / 128), 256>>>(pxb, 768, pWxp64,  pdbl, 40, 40, 768);
    sgemm64<<<dim3(1, MROWS / 128), 256>>>(pxc, 768, pWxpc64, pcm,  16, 16, 768);

    // dt_proj (fp32, K=24, softplus + bias)
    {
        dim3 grid(6, MROWS / 128);
        sgemm<<<grid, 256>>>(pdbl, 40, pWdt, dt_proj_bias, nullptr, 0,
                             pdt, 768, MROWS, 768, 24, 1);
    }

    // selective scan with fused silu(z) gate (z prefetched, exp hoisted)
    scan_kernel<<<BSZ * 48, 256>>>(px, pdt, pdbl, pcm, A_log, Dvec, pxz, py);

    // out_proj + residual(ms)
    g16(py, 768, pWout, nullptr, ms, 384, pgf, 384, 384, 768);

    // (B,L,C) -> (B,C,HW) transpose, then 3x3 depthwise conv
    {
        dim3 grid(DIMC / 32, LSEQ / 32, BSZ);
        dim3 blk(32, 8);
        transpose_LC<<<grid, blk>>>(pgf, pimg);
    }
    {
        int tot = BSZ * DIMC * 64 * 64;
        dwconv3x3<<<(tot + 255) / 256, 256>>>(pimg, dwconv_w, dwconv_b, out);
    }
}

// round 17
// speedup vs baseline: 2.3473x; 1.0385x over previous
#include <cuda_runtime.h>
#include <math.h>
#include <stdint.h>

#define MROWS  16384
#define LSEQ   4096
#define BSZ    4
#define DIMC   384
#define DINNER 768
#define DSTATE 16
#define DTRANK 24

// ---------------- scratch (device globals; allocation-free) ----------------
__device__ float g_Wr_t  [768*384];    // reduce_W^T   (K=768, N=384)
__device__ float g_Win_t [384*1536];   // in_proj_W^T
__device__ float g_Winb_t[384*768];
__device__ float g_Winc_t[384*768];
__device__ float g_Wout_t[768*384];
__device__ float g_Wxp64 [768*64];     // x_proj_W^T padded  [768][64]
__device__ float g_Wxpc64[768*64];     // x_proj_c_W^T padded [768][64]
__device__ float g_Wdt_t [24*768];

__device__ float g_msn   [MROWS*384];
__device__ float g_pann  [MROWS*384];
__device__ float g_red   [MROWS*384];
__device__ float g_conn  [MROWS*384];
__device__ float g_xz    [(size_t)MROWS*1536];
__device__ float g_xbp   [MROWS*768];
__device__ float g_xcp   [MROWS*768];
__device__ float g_x     [MROWS*768];
__device__ float g_xb    [MROWS*768];
__device__ float g_xc    [MROWS*768];
__device__ float g_dbl   [MROWS*40];
__device__ float g_dt    [MROWS*768];
__device__ float g_cm    [MROWS*16];
__device__ float g_y     [MROWS*768];
__device__ float g_gf    [MROWS*384];
__device__ float g_img   [MROWS*384];

// ---------------- helpers ----------------
__device__ __forceinline__ float silu_f(float v) {
    return v / (1.f + __expf(-v));
}

// ---------------- weight transpose: out[k*N+n] = in[n*K+k] ----------------
__global__ void wt_transpose(const float* __restrict__ in, float* __restrict__ out,
                             int N, int K) {
    int idx = blockIdx.x * blockDim.x + threadIdx.x;
    if (idx >= N * K) return;
    int n = idx % N;
    int k = idx / N;
    out[(size_t)k * N + n] = in[(size_t)n * K + k];
}

// ---------------- transpose + pad: in [Nin,K] -> out [K,64] (pad cols zero) ----
__global__ void wt_transpose_pad64(const float* __restrict__ in, float* __restrict__ out,
                                   int Nin, int K) {
    int idx = blockIdx.x * blockDim.x + threadIdx.x;
    if (idx >= K * 64) return;
    int n = idx % 64;
    int k = idx / 64;
    out[idx] = (n < Nin) ? in[(size_t)n * K + k] : 0.f;
}

// ---------------- layernorm over 384, one block (128 thr) per row ----------------
__global__ __launch_bounds__(128) void ln_kernel(const float* __restrict__ x,
                                                 const float* __restrict__ w,
                                                 const float* __restrict__ b,
                                                 float* __restrict__ out) {
    int m = blockIdx.x;
    int t = threadIdx.x;
    const float* row = x + (size_t)m * 384;
    float v0 = row[t], v1 = row[t + 128], v2 = row[t + 256];
    float s = v0 + v1 + v2;
    __shared__ float red1[4], red2[4];
    #pragma unroll
    for (int o = 16; o; o >>= 1) s += __shfl_xor_sync(0xffffffffu, s, o);
    if ((t & 31) == 0) red1[t >> 5] = s;
    __syncthreads();
    float mu = (red1[0] + red1[1] + red1[2] + red1[3]) * (1.f / 384.f);
    float d0 = v0 - mu, d1 = v1 - mu, d2 = v2 - mu;
    float q = d0 * d0 + d1 * d1 + d2 * d2;
    #pragma unroll
    for (int o = 16; o; o >>= 1) q += __shfl_xor_sync(0xffffffffu, q, o);
    if ((t & 31) == 0) red2[t >> 5] = q;
    __syncthreads();
    float var = (red2[0] + red2[1] + red2[2] + red2[3]) * (1.f / 384.f);
    float inv = rsqrtf(var + 1e-5f);
    float* o = out + (size_t)m * 384;
    o[t]       = d0 * inv * w[t]       + b[t];
    o[t + 128] = d1 * inv * w[t + 128] + b[t + 128];
    o[t + 256] = d2 * inv * w[t + 256] + b[t + 256];
}

// ---------------- SGEMM BK=16, no bounds checks (big GEMMs) ----------------
// C[M,N] = A[M,K] * Bt[K,N] (+bias,+resid). M,N mult of 128, K mult of 16.
// SPLIT: A columns k >= ksplit come from A2 (concat fusion); dead code when false.
template<bool SPLIT>
__global__ __launch_bounds__(256, 2) void sgemm16(
    const float* __restrict__ A, int lda,
    const float* __restrict__ A2, int lda2, int ksplit,
    const float* __restrict__ Bt,
    const float* __restrict__ bias,
    const float* __restrict__ resid, int ldr,
    float* __restrict__ C, int ldc,
    int N, int K)
{
    __shared__ float As[16][132];
    __shared__ float Bs[16][128];
    int tid = threadIdx.x;
    int bm = blockIdx.y * 128, bn = blockIdx.x * 128;
    int row = tid / 16, col = tid % 16;

    float acc[8][8];
    #pragma unroll
    for (int i = 0; i < 8; i++)
        #pragma unroll
        for (int j = 0; j < 8; j++) acc[i][j] = 0.f;

    int a_m = tid >> 1;
    int a_k = (tid & 1) * 8;
    int b_n = (tid & 31) * 4;
    int b_k = tid >> 5;

    const float* ap  = A + (size_t)(bm + a_m) * lda;
    const float* ap2 = SPLIT ? (A2 + (size_t)(bm + a_m) * lda2) : nullptr;
    const float* bp0 = Bt + (size_t)b_k * N + bn + b_n;

    int ktiles = K >> 4;
    for (int t = 0; t < ktiles; ++t) {
        int k0 = t * 16;
        float4 a0, a1;
        if (SPLIT) {
            int gk = k0 + a_k;
            const float* src = (gk >= ksplit) ? (ap2 + (gk - ksplit)) : (ap + gk);
            a0 = *(const float4*)src;
            a1 = *(const float4*)(src + 4);
        } else {
            a0 = *(const float4*)(ap + k0 + a_k);
            a1 = *(const float4*)(ap + k0 + a_k + 4);
        }
        float4 bv0 = *(const float4*)(bp0 + (size_t)k0 * N);
        float4 bv1 = *(const float4*)(bp0 + (size_t)(k0 + 8) * N);
        As[a_k + 0][a_m] = a0.x;
        As[a_k + 1][a_m] = a0.y;
        As[a_k + 2][a_m] = a0.z;
        As[a_k + 3][a_m] = a0.w;
        As[a_k + 4][a_m] = a1.x;
        As[a_k + 5][a_m] = a1.y;
        As[a_k + 6][a_m] = a1.z;
        As[a_k + 7][a_m] = a1.w;
        *(float4*)&Bs[b_k][b_n]     = bv0;
        *(float4*)&Bs[b_k + 8][b_n] = bv1;
        __syncthreads();
        #pragma unroll
        for (int k = 0; k < 16; ++k) {
            float a[8], b[8];
            *(float4*)(a)     = *(const float4*)&As[k][row * 8];
            *(float4*)(a + 4) = *(const float4*)&As[k][row * 8 + 4];
            *(float4*)(b)     = *(const float4*)&Bs[k][col * 8];
            *(float4*)(b + 4) = *(const float4*)&Bs[k][col * 8 + 4];
            #pragma unroll
            for (int i = 0; i < 8; i++)
                #pragma unroll
                for (int j = 0; j < 8; j++)
                    acc[i][j] = fmaf(a[i], b[j], acc[i][j]);
        }
        __syncthreads();
    }
    // epilogue
    #pragma unroll
    for (int i = 0; i < 8; i++) {
        int m = bm + row * 8 + i;
        float* crow = C + (size_t)m * ldc;
        #pragma unroll
        for (int j = 0; j < 8; j += 4) {
            int n0 = bn + col * 8 + j;
            float4 v = make_float4(acc[i][j], acc[i][j + 1], acc[i][j + 2], acc[i][j + 3]);
            if (bias) {
                const float4 bb = *(const float4*)&bias[n0];
                v.x += bb.x; v.y += bb.y; v.z += bb.z; v.w += bb.w;
            }
            if (resid) {
                const float4 rr = *(const float4*)(resid + (size_t)m * ldr + n0);
                v.x += rr.x; v.y += rr.y; v.z += rr.z; v.w += rr.w;
            }
            *(float4*)(crow + n0) = v;
        }
    }
}

// ---------------- SGEMM (round-1 verbatim; used for dt_proj K=24) ----------------
__global__ __launch_bounds__(256) void sgemm(
    const float* __restrict__ A, int lda,
    const float* __restrict__ Bt,
    const float* __restrict__ bias,
    const float* __restrict__ resid, int ldr,
    float* __restrict__ C, int ldc,
    int M, int N, int K, int act)
{
    __shared__ float As[8][132];
    __shared__ float Bs[8][128];
    int tid = threadIdx.x;
    int bm = blockIdx.y * 128, bn = blockIdx.x * 128;
    int row = tid / 16, col = tid % 16;

    float acc[8][8];
    #pragma unroll
    for (int i = 0; i < 8; i++)
        #pragma unroll
        for (int j = 0; j < 8; j++) acc[i][j] = 0.f;

    int a_m = tid / 2;
    int a_k = (tid % 2) * 4;
    int b_n = (tid % 32) * 4;
    int b_k = tid / 32;

    int ktiles = (K + 7) / 8;
    for (int t = 0; t < ktiles; ++t) {
        int k0 = t * 8;
        {
            float4 av = make_float4(0.f, 0.f, 0.f, 0.f);
            int gm = bm + a_m, gk = k0 + a_k;
            const float* ap = A + (size_t)gm * lda;
            if (gk + 3 < K) {
                av = *(const float4*)(ap + gk);
            } else {
                if (gk + 0 < K) av.x = ap[gk + 0];
                if (gk + 1 < K) av.y = ap[gk + 1];
                if (gk + 2 < K) av.z = ap[gk + 2];
                if (gk + 3 < K) av.w = ap[gk + 3];
            }
            As[a_k + 0][a_m] = av.x;
            As[a_k + 1][a_m] = av.y;
            As[a_k + 2][a_m] = av.z;
            As[a_k + 3][a_m] = av.w;
        }
        {
            float4 bv = make_float4(0.f, 0.f, 0.f, 0.f);
            int gn = bn + b_n, gk = k0 + b_k;
            if (gk < K) {
                const float* bp = Bt + (size_t)gk * N;
                if (gn + 3 < N) {
                    bv = *(const float4*)(bp + gn);
                } else {
                    if (gn + 0 < N) bv.x = bp[gn + 0];
                    if (gn + 1 < N) bv.y = bp[gn + 1];
                    if (gn + 2 < N) bv.z = bp[gn + 2];
                    if (gn + 3 < N) bv.w = bp[gn + 3];
                }
            }
            *(float4*)&Bs[b_k][b_n] = bv;
        }
        __syncthreads();
        #pragma unroll
        for (int k = 0; k < 8; ++k) {
            float a[8], b[8];
            *(float4*)(a)     = *(const float4*)&As[k][row * 8];
            *(float4*)(a + 4) = *(const float4*)&As[k][row * 8 + 4];
            *(float4*)(b)     = *(const float4*)&Bs[k][col * 8];
            *(float4*)(b + 4) = *(const float4*)&Bs[k][col * 8 + 4];
            #pragma unroll
            for (int i = 0; i < 8; i++)
                #pragma unroll
                for (int j = 0; j < 8; j++)
                    acc[i][j] = fmaf(a[i], b[j], acc[i][j]);
        }
        __syncthreads();
    }
    #pragma unroll
    for (int i = 0; i < 8; i++) {
        int m = bm + row * 8 + i;
        if (m >= M) continue;
        #pragma unroll
        for (int j = 0; j < 8; j++) {
            int n = bn + col * 8 + j;
            if (n >= N) continue;
            float v = acc[i][j];
            if (bias) v += bias[n];
            if (act == 1) {  // softplus
                v = (v > 20.f) ? v : log1pf(expf(v));
            }
            if (resid) v += resid[(size_t)m * ldr + n];
            C[(size_t)m * ldc + n] = v;
        }
    }
}

// ---------------- narrow SGEMM: tile 128x64, Bt padded [K][64] ----------------
__global__ __launch_bounds__(256) void sgemm64(
    const float* __restrict__ A, int lda,
    const float* __restrict__ Bt,          // [K][64]
    float* __restrict__ C, int ldc,
    int Nstore, int K)
{
    __shared__ float As[8][132];
    __shared__ float Bs[8][64];
    int tid = threadIdx.x;
    int bm = blockIdx.y * 128;
    int row = tid / 16, col = tid % 16;

    float acc[8][4];
    #pragma unroll
    for (int i = 0; i < 8; i++)
        #pragma unroll
        for (int j = 0; j < 4; j++) acc[i][j] = 0.f;

    int a_m = tid / 2;
    int a_k = (tid % 2) * 4;
    int b_k = tid >> 4;
    int b_n = (tid & 15) * 4;

    int ktiles = K / 8;
    for (int t = 0; t < ktiles; ++t) {
        int k0 = t * 8;
        {
            float4 av = *(const float4*)(A + (size_t)(bm + a_m) * lda + k0 + a_k);
            As[a_k + 0][a_m] = av.x;
            As[a_k + 1][a_m] = av.y;
            As[a_k + 2][a_m] = av.z;
            As[a_k + 3][a_m] = av.w;
        }
        if (tid < 128) {
            float4 bv = *(const float4*)(Bt + (size_t)(k0 + b_k) * 64 + b_n);
            *(float4*)&Bs[b_k][b_n] = bv;
        }
        __syncthreads();
        #pragma unroll
        for (int k = 0; k < 8; ++k) {
            float a[8], b[4];
            *(float4*)(a)     = *(const float4*)&As[k][row * 8];
            *(float4*)(a + 4) = *(const float4*)&As[k][row * 8 + 4];
            *(float4*)(b)     = *(const float4*)&Bs[k][col * 4];
            #pragma unroll
            for (int i = 0; i < 8; i++)
                #pragma unroll
                for (int j = 0; j < 4; j++)
                    acc[i][j] = fmaf(a[i], b[j], acc[i][j]);
        }
        __syncthreads();
    }
    #pragma unroll
    for (int i = 0; i < 8; i++) {
        int m = bm + row * 8 + i;
        int n0 = col * 4;
        if (n0 >= Nstore) continue;
        *(float4*)(C + (size_t)m * ldc + n0) =
            make_float4(acc[i][0], acc[i][1], acc[i][2], acc[i][3]);
    }
}

// ---------------- causal depthwise conv1d (K=4) + SiLU ----------------
__global__ void dwconv1d_silu(const float* __restrict__ x, int xstride,
                              const float* __restrict__ w,
                              const float* __restrict__ bias,
                              float* __restrict__ out) {
    int idx = blockIdx.x * blockDim.x + threadIdx.x;
    if (idx >= MROWS * DINNER) return;
    int d = idx % DINNER;
    int m = idx / DINNER;
    int l = m & (LSEQ - 1);
    float acc = bias[d];
    #pragma unroll
    for (int k = 0; k < 4; k++) {
        int ll = l - 3 + k;
        if (ll >= 0)
            acc += w[d * 4 + k] * x[(size_t)(m + (ll - l)) * xstride + d];
    }
    out[(size_t)m * DINNER + d] = silu_f(acc);
}

// ---------------- selective scan: z prefetched, exp hoisted, tile double-buffer
// Register-prefetch next tile's 5 global loads during current tile's compute.
__global__ __launch_bounds__(256) void scan_kernel(
    const float* __restrict__ u,
    const float* __restrict__ dt,
    const float* __restrict__ dbl,
    const float* __restrict__ Cm,
    const float* __restrict__ A_log,
    const float* __restrict__ Dp,
    const float* __restrict__ xz,   // z at column offset 768, stride 1536
    float* __restrict__ y)
{
    int b  = blockIdx.x / 48;
    int d0 = (blockIdx.x % 48) * 16;
    int tid = threadIdx.x;
    int dl = tid / 16;
    int n  = tid % 16;
    int d = d0 + dl;
    float a = -expf(A_log[d * 16 + n]);
    float Dv = Dp[d];
    __shared__ float sdt[16][16], su[16][16], sB[16][17], sC[16][17], sz[16][16];
    float h = 0.f;
    size_t base = (size_t)b * LSEQ;
    int lo = tid / 16, c = tid % 16;

    float rdt, ru, rB, rC, rz;
    {
        size_t m = base + lo;
        rdt = dt[m * 768 + d0 + c];
        ru  = u [m * 768 + d0 + c];
        rB  = dbl[m * 40 + 24 + c];
        rC  = Cm [m * 16 + c];
        rz  = xz[m * 1536 + 768 + d0 + c];
    }

    for (int l0 = 0; l0 < LSEQ; l0 += 16) {
        sdt[lo][c] = rdt;
        su [lo][c] = ru;
        sB [lo][c] = rB;
        sC [lo][c] = rC;
        sz [lo][c] = rz;
        __syncthreads();
        // issue next tile's loads (latency hidden under compute below)
        if (l0 + 16 < LSEQ) {
            size_t m = base + l0 + 16 + lo;
            rdt = dt[m * 768 + d0 + c];
            ru  = u [m * 768 + d0 + c];
            rB  = dbl[m * 40 + 24 + c];
            rC  = Cm [m * 16 + c];
            rz  = xz[m * 1536 + 768 + d0 + c];
        }
        // phase 0: h-independent precompute (fully pipelined)
        float e[16], g[16];
        #pragma unroll
        for (int s = 0; s < 16; ++s) {
            float dtv = sdt[s][dl];
            e[s] = __expf(dtv * a);
            g[s] = dtv * su[s][dl] * sB[s][n];
        }
        // phase 1: bare recurrence chain + partial products
        float p[16];
        #pragma unroll
        for (int s = 0; s < 16; ++s) {
            h = fmaf(e[s], h, g[s]);
            p[s] = h * sC[s][n];
        }
        // phase 2: pipelined reductions + gated stores
        #pragma unroll
        for (int s = 0; s < 16; ++s) {
            float q = p[s];
            q += __shfl_xor_sync(0xffffffffu, q, 8);
            q += __shfl_xor_sync(0xffffffffu, q, 4);
            q += __shfl_xor_sync(0xffffffffu, q, 2);
            q += __shfl_xor_sync(0xffffffffu, q, 1);
            if (n == 0) {
                size_t mm = base + l0 + s;
                y[mm * 768 + d] = (q + su[s][dl] * Dv) * silu_f(sz[s][dl]);
            }
        }
        __syncthreads();
    }
}

// ---------------- (B,L,C) -> (B,C,L) transpose ----------------
__global__ void transpose_LC(const float* __restrict__ in, float* __restrict__ out) {
    __shared__ float t[32][33];
    int bb = blockIdx.z;
    int c0 = blockIdx.x * 32, l0 = blockIdx.y * 32;
    const float* ip = in + (size_t)bb * LSEQ * DIMC;
    float* op = out + (size_t)bb * DIMC * LSEQ;
    int tx = threadIdx.x, ty = threadIdx.y;
    #pragma unroll
    for (int i = 0; i < 32; i += 8)
        t[ty + i][tx] = ip[(size_t)(l0 + ty + i) * DIMC + c0 + tx];
    __syncthreads();
    #pragma unroll
    for (int i = 0; i < 32; i += 8)
        op[(size_t)(c0 + ty + i) * LSEQ + l0 + tx] = t[tx][ty + i];
}

// ---------------- final 3x3 depthwise conv (SAME) on (B,C,64,64) ----------------
__global__ void dwconv3x3(const float* __restrict__ img, const float* __restrict__ w,
                          const float* __restrict__ bias, float* __restrict__ out) {
    int idx = blockIdx.x * blockDim.x + threadIdx.x;
    if (idx >= BSZ * DIMC * 64 * 64) return;
    int wv = idx & 63;
    int h  = (idx >> 6) & 63;
    int c  = (idx >> 12) % DIMC;
    int b  = idx / (DIMC * 4096);
    const float* ip = img + ((size_t)b * DIMC + c) * 4096;
    const float* wc = w + c * 9;
    float acc = bias[c];
    #pragma unroll
    for (int dh = -1; dh <= 1; dh++) {
        int hh = h + dh;
        if (hh < 0 || hh >= 64) continue;
        #pragma unroll
        for (int dw = -1; dw <= 1; dw++) {
            int ww = wv + dw;
            if (ww < 0 || ww >= 64) continue;
            acc += wc[(dh + 1) * 3 + (dw + 1)] * ip[hh * 64 + ww];
        }
    }
    out[idx] = acc;
}

// ---------------- host ----------------
static void g16(const float* A, int lda, const float* Bt,
                const float* bias, const float* resid, int ldr,
                float* C, int ldc, int N, int K) {
    dim3 grid(N / 128, MROWS / 128);
    sgemm16<false><<<grid, 256>>>(A, lda, nullptr, 0, 0, Bt, bias, resid, ldr,
                                  C, ldc, N, K);
}

extern "C" void kernel_launch(void* const* d_in, const int* in_sizes, int n_in,
                              void* d_out, int out_size) {
    const float* ms          = (const float*)d_in[0];
    const float* pan         = (const float*)d_in[1];
    const float* reduce_W    = (const float*)d_in[2];
    const float* reduce_b    = (const float*)d_in[3];
    const float* ln1_w       = (const float*)d_in[4];
    const float* ln1_b       = (const float*)d_in[5];
    const float* ln2_w       = (const float*)d_in[6];
    const float* ln2_b       = (const float*)d_in[7];
    const float* ln3_w       = (const float*)d_in[8];
    const float* ln3_b       = (const float*)d_in[9];
    const float* in_proj_W   = (const float*)d_in[10];
    const float* in_proj_b_W = (const float*)d_in[11];
    const float* in_proj_c_W = (const float*)d_in[12];
    const float* conv_w      = (const float*)d_in[13];
    const float* conv_bias   = (const float*)d_in[14];
    const float* conv_b_w    = (const float*)d_in[15];
    const float* conv_b_bias = (const float*)d_in[16];
    const float* conv_c_w    = (const float*)d_in[17];
    const float* conv_c_bias = (const float*)d_in[18];
    const float* x_proj_W    = (const float*)d_in[19];
    const float* x_proj_c_W  = (const float*)d_in[20];
    const float* dt_proj_W   = (const float*)d_in[21];
    const float* dt_proj_bias= (const float*)d_in[22];
    const float* A_log       = (const float*)d_in[23];
    const float* Dvec        = (const float*)d_in[24];
    const float* out_proj_W  = (const float*)d_in[25];
    const float* dwconv_w    = (const float*)d_in[26];
    const float* dwconv_b    = (const float*)d_in[27];
    float* out = (float*)d_out;

    float *pWr, *pWin, *pWinb, *pWinc, *pWout, *pWxp64, *pWxpc64, *pWdt;
    float *pmsn, *ppann, *pred, *pconn, *pxz, *pxbp, *pxcp;
    float *px, *pxb, *pxc, *pdbl, *pdt, *pcm, *py, *pgf, *pimg;
    cudaGetSymbolAddress((void**)&pWr,     g_Wr_t);
    cudaGetSymbolAddress((void**)&pWin,    g_Win_t);
    cudaGetSymbolAddress((void**)&pWinb,   g_Winb_t);
    cudaGetSymbolAddress((void**)&pWinc,   g_Winc_t);
    cudaGetSymbolAddress((void**)&pWout,   g_Wout_t);
    cudaGetSymbolAddress((void**)&pWxp64,  g_Wxp64);
    cudaGetSymbolAddress((void**)&pWxpc64, g_Wxpc64);
    cudaGetSymbolAddress((void**)&pWdt,    g_Wdt_t);
    cudaGetSymbolAddress((void**)&pmsn,    g_msn);
    cudaGetSymbolAddress((void**)&ppann,   g_pann);
    cudaGetSymbolAddress((void**)&pred,    g_red);
    cudaGetSymbolAddress((void**)&pconn,   g_conn);
    cudaGetSymbolAddress((void**)&pxz,     g_xz);
    cudaGetSymbolAddress((void**)&pxbp,    g_xbp);
    cudaGetSymbolAddress((void**)&pxcp,    g_xcp);
    cudaGetSymbolAddress((void**)&px,      g_x);
    cudaGetSymbolAddress((void**)&pxb,     g_xb);
    cudaGetSymbolAddress((void**)&pxc,     g_xc);
    cudaGetSymbolAddress((void**)&pdbl,    g_dbl);
    cudaGetSymbolAddress((void**)&pdt,     g_dt);
    cudaGetSymbolAddress((void**)&pcm,     g_cm);
    cudaGetSymbolAddress((void**)&py,      g_y);
    cudaGetSymbolAddress((void**)&pgf,     g_gf);
    cudaGetSymbolAddress((void**)&pimg,    g_img);

    auto wt = [](const float* in, float* o, int N, int K) {
        int tot = N * K;
        wt_transpose<<<(tot + 255) / 256, 256>>>(in, o, N, K);
    };

    // launches 1-5
    wt(reduce_W,  pWr,  384, 768);                          // 1
    wt(in_proj_W, pWin, 1536, 384);                         // 2
    ln_kernel<<<MROWS, 128>>>(ms,  ln1_w, ln1_b, pmsn);     // 3
    ln_kernel<<<MROWS, 128>>>(pan, ln2_w, ln2_b, ppann);    // 4
    wt(in_proj_b_W, pWinb, 768, 384);                       // 5

    // 6: reduce GEMM with fused concat (A = [ms | pan])
    {
        dim3 grid(384 / 128, MROWS / 128);
        sgemm16<true><<<grid, 256>>>(ms, 384, pan, 384, 384, pWr,
                                     reduce_b, nullptr, 0, pred, 384, 384, 768);
    }

    // in_proj GEMM
    g16(pmsn, 384, pWin, nullptr, nullptr, 0, pxz, 1536, 1536, 384);

    ln_kernel<<<MROWS, 128>>>(pred, ln3_w, ln3_b, pconn);

    wt(in_proj_c_W, pWinc, 768, 384);
    wt(dt_proj_W,   pWdt,  768, 24);
    wt(out_proj_W,  pWout, 384, 768);
    wt_transpose_pad64<<<(768 * 64 + 255) / 256, 256>>>(x_proj_W,   pWxp64,  40, 768);
    wt_transpose_pad64<<<(768 * 64 + 255) / 256, 256>>>(x_proj_c_W, pWxpc64, 16, 768);

    g16(ppann, 384, pWinb, nullptr, nullptr, 0, pxbp, 768, 768, 384);
    g16(pconn, 384, pWinc, nullptr, nullptr, 0, pxcp, 768, 768, 384);

    // depthwise causal convs + SiLU
    {
        int tot = MROWS * DINNER;
        int blocks = (tot + 255) / 256;
        dwconv1d_silu<<<blocks, 256>>>(pxz,  1536, conv_w,   conv_bias,   px);
        dwconv1d_silu<<<blocks, 256>>>(pxbp, 768,  conv_b_w, conv_b_bias, pxb);
        dwconv1d_silu<<<blocks, 256>>>(pxcp, 768,  conv_c_w, conv_c_bias, pxc);
    }

    // narrow projections (BN=64 kernel, padded transposed weights)
    sgemm64<<<dim3(1, MROWS / 128), 256>>>(pxb, 768, pWxp64,  pdbl, 40, 40, 768);
    sgemm64<<<dim3(1, MROWS / 128), 256>>>(pxc, 768, pWxpc64, pcm,  16, 16, 768);

    // dt_proj (fp32, K=24, softplus + bias)
    {
        dim3 grid(6, MROWS / 128);
        sgemm<<<grid, 256>>>(pdbl, 40, pWdt, dt_proj_bias, nullptr, 0,
                             pdt, 768, MROWS, 768, 24, 1);
    }

    // selective scan (z prefetched, exp hoisted, tile double-buffered)
    scan_kernel<<<BSZ * 48, 256>>>(px, pdt, pdbl, pcm, A_log, Dvec, pxz, py);

    // out_proj + residual(ms)
    g16(py, 768, pWout, nullptr, ms, 384, pgf, 384, 384, 768);

    // (B,L,C) -> (B,C,HW) transpose, then 3x3 depthwise conv
    {
        dim3 grid(DIMC / 32, LSEQ / 32, BSZ);
        dim3 blk(32, 8);
        transpose_LC<<<grid, blk>>>(pgf, pimg);
    }
    {
        int tot = BSZ * DIMC * 64 * 64;
        dwconv3x3<<<(tot + 255) / 256, 256>>>(pimg, dwconv_w, dwconv_b, out);
    }
}